// round 13
// baseline (speedup 1.0000x reference)
#include <cuda_runtime.h>
#include <cuda_bf16.h>
#include <cstdint>

#define S_ 2048
#define D_ 512
#define H_ 8
#define DK_ 64
#define BH_ 32
#define TOK_ 8192
#define OUT_ELEMS 4194304ull
#define ATTN_ELEMS 134217728ull
#define PO_ 4194304ull

__device__ uint16_t g_xnh[3ull * TOK_ * D_];
__device__ uint16_t g_xnl[3ull * TOK_ * D_];
__device__ uint16_t g_wh[4ull * 512 * 512];
__device__ uint16_t g_wl[4ull * 512 * 512];
__device__ uint16_t g_phh[3ull * PO_];
__device__ uint16_t g_phl[3ull * PO_];
__device__ uint16_t g_xh[(size_t)TOK_ * D_];
__device__ uint16_t g_xl[(size_t)TOK_ * D_];
__device__ float g_rinv[BH_ * S_];
__device__ float g_attn_scratch[ATTN_ELEMS];

__device__ __forceinline__ void hmma(float c[4], const uint32_t a[4], uint32_t b0, uint32_t b1) {
    asm("mma.sync.aligned.m16n8k16.row.col.f32.bf16.bf16.f32 "
        "{%0,%1,%2,%3},{%4,%5,%6,%7},{%8,%9},{%0,%1,%2,%3};"
        : "+f"(c[0]), "+f"(c[1]), "+f"(c[2]), "+f"(c[3])
        : "r"(a[0]), "r"(a[1]), "r"(a[2]), "r"(a[3]), "r"(b0), "r"(b1));
}
__device__ __forceinline__ void ldsm4(uint32_t& r0, uint32_t& r1, uint32_t& r2, uint32_t& r3,
                                      uint32_t addr) {
    asm volatile("ldmatrix.sync.aligned.m8n8.x4.shared.b16 {%0,%1,%2,%3}, [%4];"
                 : "=r"(r0), "=r"(r1), "=r"(r2), "=r"(r3) : "r"(addr));
}
__device__ __forceinline__ void ldsm4t(uint32_t& r0, uint32_t& r1, uint32_t& r2, uint32_t& r3,
                                       uint32_t addr) {
    asm volatile("ldmatrix.sync.aligned.m8n8.x4.trans.shared.b16 {%0,%1,%2,%3}, [%4];"
                 : "=r"(r0), "=r"(r1), "=r"(r2), "=r"(r3) : "r"(addr));
}
__device__ __forceinline__ void cpa16(uint32_t dst, const void* src) {
    asm volatile("cp.async.cg.shared.global [%0], [%1], 16;" :: "r"(dst), "l"(src));
}
#define CP_COMMIT() asm volatile("cp.async.commit_group;")
#define CP_WAIT0()  asm volatile("cp.async.wait_group 0;")
#define CP_WAIT1()  asm volatile("cp.async.wait_group 1;")
__device__ __forceinline__ void splitpack(float f0, float f1, uint32_t& h, uint32_t& l) {
    asm("cvt.rn.bf16x2.f32 %0, %1, %2;" : "=r"(h) : "f"(f1), "f"(f0));
    float g0 = __uint_as_float(h << 16);
    float g1 = __uint_as_float(h & 0xffff0000u);
    asm("cvt.rn.bf16x2.f32 %0, %1, %2;" : "=r"(l) : "f"(f1 - g1), "f"(f0 - g0));
}
__device__ __forceinline__ float fexp(float x) {
    float t = x * 1.4426950408889634f;
    t = fmaxf(t, -126.0f);
    float z = t + 12582912.0f;
    int   n = (__float_as_int(z) & 0x7FFFFF) - 0x400000;
    float f = t - (z - 12582912.0f);
    float p = 1.5403530e-4f;
    p = fmaf(p, f, 1.3333558e-3f);
    p = fmaf(p, f, 9.6181291e-3f);
    p = fmaf(p, f, 5.5504109e-2f);
    p = fmaf(p, f, 2.4022651e-1f);
    p = fmaf(p, f, 6.9314718e-1f);
    p = fmaf(p, f, 1.0f);
    return __int_as_float(__float_as_int(p) + (n << 23));
}

// ---------------- K1: LayerNorm -> split bf16 ----------------
__global__ void ln_split(const float* __restrict__ q, const float* __restrict__ k,
                         const float* __restrict__ v, const float* __restrict__ w,
                         const float* __restrict__ b,
                         uint16_t* __restrict__ xh, uint16_t* __restrict__ xl) {
    const int row = blockIdx.x, which = blockIdx.y, tid = threadIdx.x;
    const float* src = (which == 0) ? q : (which == 1) ? k : v;
    float4 x = *(const float4*)(src + (size_t)row * D_ + tid * 4);
    float s  = x.x + x.y + x.z + x.w;
    float ss = x.x * x.x + x.y * x.y + x.z * x.z + x.w * x.w;
    __shared__ float red[2][4];
    #pragma unroll
    for (int o = 16; o; o >>= 1) {
        s  += __shfl_xor_sync(0xffffffffu, s, o);
        ss += __shfl_xor_sync(0xffffffffu, ss, o);
    }
    if ((tid & 31) == 0) { red[0][tid >> 5] = s; red[1][tid >> 5] = ss; }
    __syncthreads();
    s  = red[0][0] + red[0][1] + red[0][2] + red[0][3];
    ss = red[1][0] + red[1][1] + red[1][2] + red[1][3];
    const float mu  = s * (1.0f / D_);
    const float var = ss * (1.0f / D_) - mu * mu;
    const float r   = rsqrtf(var + 1e-5f);
    float4 wv = *(const float4*)(w + tid * 4);
    float4 bv = *(const float4*)(b + tid * 4);
    float o0 = (x.x - mu) * r * wv.x + bv.x;
    float o1 = (x.y - mu) * r * wv.y + bv.y;
    float o2 = (x.z - mu) * r * wv.z + bv.z;
    float o3 = (x.w - mu) * r * wv.w + bv.w;
    uint32_t h01, l01, h23, l23;
    splitpack(o0, o1, h01, l01); splitpack(o2, o3, h23, l23);
    size_t base = ((size_t)which * TOK_ + row) * D_ + tid * 4;
    *(uint32_t*)(xh + base) = h01; *(uint32_t*)(xh + base + 2) = h23;
    *(uint32_t*)(xl + base) = l01; *(uint32_t*)(xl + base + 2) = l23;
}

// ---------------- K2: split weights ----------------
__global__ void wsplit(const float* __restrict__ Wq, const float* __restrict__ Wk,
                       const float* __restrict__ Wv, const float* __restrict__ Wo,
                       uint16_t* __restrict__ wh, uint16_t* __restrict__ wl) {
    const int row = blockIdx.x, mat = blockIdx.y, tid = threadIdx.x;
    const float* W = (mat == 0) ? Wq : (mat == 1) ? Wk : (mat == 2) ? Wv : Wo;
    float4 x = *(const float4*)(W + (size_t)row * 512 + tid * 4);
    uint32_t h01, l01, h23, l23;
    splitpack(x.x, x.y, h01, l01); splitpack(x.z, x.w, h23, l23);
    size_t base = ((size_t)mat * 512 + row) * 512 + tid * 4;
    *(uint32_t*)(wh + base) = h01; *(uint32_t*)(wh + base + 2) = h23;
    *(uint32_t*)(wl + base) = l01; *(uint32_t*)(wl + base + 2) = l23;
}

// ---------------- K3: batched projections / K5: out-proj + parallel rescale ----------------
__global__ __launch_bounds__(256, 2)
void gemm_mma(const uint16_t* __restrict__ Ab, const uint16_t* __restrict__ Alb,
              const uint16_t* __restrict__ Bb, const uint16_t* __restrict__ Blb,
              const float* __restrict__ b0p, const float* __restrict__ b1p,
              const float* __restrict__ b2p,
              uint16_t* __restrict__ Dh, uint16_t* __restrict__ Dl,
              float* __restrict__ Df, int mode,
              float* __restrict__ attn, const float* __restrict__ rinvp) {
    extern __shared__ uint16_t sm[];
    const int tid = threadIdx.x;
    if (mode == 0 && blockIdx.z == 1) {
        int linear = blockIdx.y * 4 + blockIdx.x;
        int bh = linear >> 3, r0 = (linear & 7) * 256;
        for (int row = 0; row < 256; row++) {
            float inv = rinvp[bh * S_ + r0 + row];
            float4* p = (float4*)(attn + ((size_t)bh * S_ + r0 + row) * S_);
            float4 a = p[tid], b = p[tid + 256];
            a.x *= inv; a.y *= inv; a.z *= inv; a.w *= inv;
            b.x *= inv; b.y *= inv; b.z *= inv; b.w *= inv;
            p[tid] = a; p[tid + 256] = b;
        }
        return;
    }
    const int w = tid >> 5, lane = tid & 31;
    const int gid = lane >> 2, tig = lane & 3;
    const int n0 = blockIdx.x * 128, m0 = blockIdx.y * 128;
    const int mz = (mode == 1) ? blockIdx.z : 0;
    const uint16_t* Ah = Ab  + (size_t)mz * TOK_ * D_;
    const uint16_t* Al = Alb + (size_t)mz * TOK_ * D_;
    const uint16_t* Bh = Bb  + (size_t)mz * 512 * 512;
    const uint16_t* Bl = Blb + (size_t)mz * 512 * 512;
    const float* bias = (mz == 0) ? b0p : (mz == 1) ? b1p : b2p;
    const int wm = w >> 2, wn = w & 3;
    const uint32_t sbase = (uint32_t)__cvta_generic_to_shared(sm);
    const int srow = tid >> 1;
    const uint32_t soff = (uint32_t)(srow * 80 + (tid & 1) * 32);
    const size_t goff = (size_t)srow * 512 + (tid & 1) * 16;

    float acc[4][4][4];
    #pragma unroll
    for (int i = 0; i < 4; i++)
        #pragma unroll
        for (int j = 0; j < 4; j++)
            #pragma unroll
            for (int kq = 0; kq < 4; kq++) acc[i][j][kq] = 0.f;

    {
        uint32_t b = sbase;
        cpa16(b + soff,          Ah + (size_t)m0 * 512 + goff);
        cpa16(b + soff + 16,     Ah + (size_t)m0 * 512 + goff + 8);
        cpa16(b + 10240 + soff,      Al + (size_t)m0 * 512 + goff);
        cpa16(b + 10240 + soff + 16, Al + (size_t)m0 * 512 + goff + 8);
        cpa16(b + 20480 + soff,      Bh + (size_t)n0 * 512 + goff);
        cpa16(b + 20480 + soff + 16, Bh + (size_t)n0 * 512 + goff + 8);
        cpa16(b + 30720 + soff,      Bl + (size_t)n0 * 512 + goff);
        cpa16(b + 30720 + soff + 16, Bl + (size_t)n0 * 512 + goff + 8);
        CP_COMMIT();
    }
    for (int c = 0; c < 16; c++) {
        if (c + 1 < 16) {
            uint32_t b = sbase + ((c + 1) & 1) * 40960;
            size_t g = goff + (c + 1) * 32;
            cpa16(b + soff,          Ah + (size_t)m0 * 512 + g);
            cpa16(b + soff + 16,     Ah + (size_t)m0 * 512 + g + 8);
            cpa16(b + 10240 + soff,      Al + (size_t)m0 * 512 + g);
            cpa16(b + 10240 + soff + 16, Al + (size_t)m0 * 512 + g + 8);
            cpa16(b + 20480 + soff,      Bh + (size_t)n0 * 512 + g);
            cpa16(b + 20480 + soff + 16, Bh + (size_t)n0 * 512 + g + 8);
            cpa16(b + 30720 + soff,      Bl + (size_t)n0 * 512 + g);
            cpa16(b + 30720 + soff + 16, Bl + (size_t)n0 * 512 + g + 8);
            CP_COMMIT();
            CP_WAIT1();
        } else {
            CP_WAIT0();
        }
        __syncthreads();
        const uint16_t* sAh = sm + (size_t)(c & 1) * 20480;
        const uint16_t* sAl = sAh + 5120;
        const uint16_t* sBh = sAh + 10240;
        const uint16_t* sBl = sAh + 15360;
        #pragma unroll
        for (int ks = 0; ks < 2; ks++) {
            const int dk = ks * 16 + 2 * tig;
            uint32_t ah[4][4], al[4][4], bhf[4][2], blf[4][2];
            #pragma unroll
            for (int mt = 0; mt < 4; mt++) {
                int ar = wm * 64 + mt * 16 + gid;
                ah[mt][0] = *(const uint32_t*)(sAh + ar * 40 + dk);
                ah[mt][1] = *(const uint32_t*)(sAh + (ar + 8) * 40 + dk);
                ah[mt][2] = *(const uint32_t*)(sAh + ar * 40 + dk + 8);
                ah[mt][3] = *(const uint32_t*)(sAh + (ar + 8) * 40 + dk + 8);
                al[mt][0] = *(const uint32_t*)(sAl + ar * 40 + dk);
                al[mt][1] = *(const uint32_t*)(sAl + (ar + 8) * 40 + dk);
                al[mt][2] = *(const uint32_t*)(sAl + ar * 40 + dk + 8);
                al[mt][3] = *(const uint32_t*)(sAl + (ar + 8) * 40 + dk + 8);
            }
            #pragma unroll
            for (int nt = 0; nt < 4; nt++) {
                int br = wn * 32 + nt * 8 + gid;
                bhf[nt][0] = *(const uint32_t*)(sBh + br * 40 + dk);
                bhf[nt][1] = *(const uint32_t*)(sBh + br * 40 + dk + 8);
                blf[nt][0] = *(const uint32_t*)(sBl + br * 40 + dk);
                blf[nt][1] = *(const uint32_t*)(sBl + br * 40 + dk + 8);
            }
            #pragma unroll
            for (int mt = 0; mt < 4; mt++)
                #pragma unroll
                for (int nt = 0; nt < 4; nt++) {
                    hmma(acc[mt][nt], ah[mt], bhf[nt][0], bhf[nt][1]);
                    hmma(acc[mt][nt], al[mt], bhf[nt][0], bhf[nt][1]);
                    hmma(acc[mt][nt], ah[mt], blf[nt][0], blf[nt][1]);
                }
        }
        __syncthreads();
    }
    #pragma unroll
    for (int mt = 0; mt < 4; mt++) {
        int row0 = m0 + wm * 64 + mt * 16 + gid, row1 = row0 + 8;
        #pragma unroll
        for (int nt = 0; nt < 4; nt++) {
            int nc = n0 + wn * 32 + nt * 8 + 2 * tig;
            float b0 = bias[nc], b1 = bias[nc + 1];
            float c00 = acc[mt][nt][0] + b0, c01 = acc[mt][nt][1] + b1;
            float c10 = acc[mt][nt][2] + b0, c11 = acc[mt][nt][3] + b1;
            if (mode == 0) {
                *(float2*)(Df + (size_t)row0 * 512 + nc) = make_float2(c00, c01);
                *(float2*)(Df + (size_t)row1 * 512 + nc) = make_float2(c10, c11);
            } else {
                int h = nc >> 6, dd = nc & 63;
                uint32_t hh, ll;
                int bb = row0 >> 11, tk = row0 & 2047;
                size_t o = ((size_t)mz * PO_) + (((size_t)(bb * H_ + h)) * S_ + tk) * DK_ + dd;
                splitpack(c00, c01, hh, ll);
                *(uint32_t*)(Dh + o) = hh; *(uint32_t*)(Dl + o) = ll;
                bb = row1 >> 11; tk = row1 & 2047;
                o = ((size_t)mz * PO_) + (((size_t)(bb * H_ + h)) * S_ + tk) * DK_ + dd;
                splitpack(c10, c11, hh, ll);
                *(uint32_t*)(Dh + o) = hh; *(uint32_t*)(Dl + o) = ll;
            }
        }
    }
}

// ---------------- K4: fused attention, P tile staged in smem, coalesced attn stores ----
__global__ __launch_bounds__(256, 2)
void attn_mma(const uint16_t* __restrict__ ph, const uint16_t* __restrict__ pl,
              const float* __restrict__ pos, float* __restrict__ attn,
              float* __restrict__ rinv,
              uint16_t* __restrict__ xh, uint16_t* __restrict__ xl) {
    extern __shared__ uint16_t sm[];
    uint16_t* QH  = sm;
    uint16_t* QL  = sm + 9216;
    float* Ps = (float*)(sm + 36864);   // byte offset 73728: P tile [128][68] fp32
    const int tid = threadIdx.x, w = tid >> 5, lane = tid & 31;
    const int gid = lane >> 2, tig = lane & 3;
    const int qt = blockIdx.x, bh = blockIdx.y, q0 = qt * 128;
    const uint16_t* qg  = ph;
    const uint16_t* qgl = pl;
    const uint16_t* kg  = ph + PO_;
    const uint16_t* kgl = pl + PO_;
    const uint16_t* vg  = ph + 2 * PO_;
    const uint16_t* vgl = pl + 2 * PO_;

    const uint32_t sbase = (uint32_t)__cvta_generic_to_shared(sm);
    const uint32_t loK = (lane & 7) * 144 + (lane >> 3) * 16;
    const uint32_t loV = (lane & 15) * 144 + (lane >> 4) * 16;
    const int vrow = tid >> 2;
    const uint32_t voff = (uint32_t)(vrow * 144 + (tid & 3) * 32);
    const size_t vgoff = (size_t)(tid & 3) * 16;

    {
        int row = tid >> 1, half = (tid & 1) * 32;
        const uint4* s1 = (const uint4*)(qg  + ((size_t)bh * S_ + q0 + row) * DK_ + half);
        const uint4* s2 = (const uint4*)(qgl + ((size_t)bh * S_ + q0 + row) * DK_ + half);
        uint4* d1 = (uint4*)(QH + row * 72 + half);
        uint4* d2 = (uint4*)(QL + row * 72 + half);
        #pragma unroll
        for (int j = 0; j < 4; j++) { d1[j] = s1[j]; d2[j] = s2[j]; }
    }
    __syncthreads();
    uint32_t qfh[4][4], qfl[4][4];
    {
        int qr = w * 16 + gid;
        #pragma unroll
        for (int ks = 0; ks < 4; ks++) {
            int dc = ks * 16 + 2 * tig;
            qfh[ks][0] = *(const uint32_t*)(QH + qr * 72 + dc);
            qfh[ks][1] = *(const uint32_t*)(QH + (qr + 8) * 72 + dc);
            qfh[ks][2] = *(const uint32_t*)(QH + qr * 72 + dc + 8);
            qfh[ks][3] = *(const uint32_t*)(QH + (qr + 8) * 72 + dc + 8);
            qfl[ks][0] = *(const uint32_t*)(QL + qr * 72 + dc);
            qfl[ks][1] = *(const uint32_t*)(QL + (qr + 8) * 72 + dc);
            qfl[ks][2] = *(const uint32_t*)(QL + qr * 72 + dc + 8);
            qfl[ks][3] = *(const uint32_t*)(QL + (qr + 8) * 72 + dc + 8);
        }
    }
    __syncthreads();

    const int rl0 = w * 16 + gid, rl1 = rl0 + 8;      // local row ids in block
    const int r0 = q0 + rl0, r1 = q0 + rl1;
    float sum0 = 0.f, sum1 = 0.f;
    float accv[8][4];
    #pragma unroll
    for (int i = 0; i < 8; i++)
        #pragma unroll
        for (int j = 0; j < 4; j++) accv[i][j] = 0.f;
    uint32_t a01h[4], a01l[4];

    {
        size_t g = ((size_t)bh * S_ + vrow) * DK_ + vgoff;
        uint32_t b = sbase;
        cpa16(b + voff,              kg + g);
        cpa16(b + voff + 16,         kg + g + 8);
        cpa16(b + 9216 + voff,       kgl + g);
        cpa16(b + 9216 + voff + 16,  kgl + g + 8);
        cpa16(b + 18432 + voff,      vg + g);
        cpa16(b + 18432 + voff + 16, vg + g + 8);
        cpa16(b + 27648 + voff,      vgl + g);
        cpa16(b + 27648 + voff + 16, vgl + g + 8);
        CP_COMMIT();
    }
    for (int kt = 0; kt < 32; kt++) {
        const int k0 = kt * 64;
        if (kt + 1 < 32) {
            size_t g = ((size_t)bh * S_ + (kt + 1) * 64 + vrow) * DK_ + vgoff;
            uint32_t b = sbase + ((kt + 1) & 1) * 36864;
            cpa16(b + voff,              kg + g);
            cpa16(b + voff + 16,         kg + g + 8);
            cpa16(b + 9216 + voff,       kgl + g);
            cpa16(b + 9216 + voff + 16,  kgl + g + 8);
            cpa16(b + 18432 + voff,      vg + g);
            cpa16(b + 18432 + voff + 16, vg + g + 8);
            cpa16(b + 27648 + voff,      vgl + g);
            cpa16(b + 27648 + voff + 16, vgl + g + 8);
            CP_COMMIT();
            CP_WAIT1();
        } else {
            CP_WAIT0();
        }
        __syncthreads();
        const uint32_t bb0 = sbase + (kt & 1) * 36864;
        const uint32_t khb = bb0, klb = bb0 + 9216;
        const uint32_t vshb = bb0 + 18432, vslb = bb0 + 27648;

        #pragma unroll
        for (int nt = 0; nt < 8; nt++) {
            float s[4] = {0.f, 0.f, 0.f, 0.f};
            uint32_t kb[8], klo[8];
            ldsm4(kb[0], kb[1], kb[2], kb[3], khb + nt * 1152 + loK);
            ldsm4(kb[4], kb[5], kb[6], kb[7], khb + nt * 1152 + 64 + loK);
            ldsm4(klo[0], klo[1], klo[2], klo[3], klb + nt * 1152 + loK);
            ldsm4(klo[4], klo[5], klo[6], klo[7], klb + nt * 1152 + 64 + loK);
            #pragma unroll
            for (int ks = 0; ks < 4; ks++) {
                hmma(s, qfh[ks], kb[2 * ks], kb[2 * ks + 1]);
                hmma(s, qfl[ks], kb[2 * ks], kb[2 * ks + 1]);
                hmma(s, qfh[ks], klo[2 * ks], klo[2 * ks + 1]);
            }
            int col = k0 + nt * 8 + 2 * tig;
            float2 p0 = *(const float2*)(pos + (size_t)r0 * S_ + col);
            float2 p1 = *(const float2*)(pos + (size_t)r1 * S_ + col);
            float e0 = fexp(fmaf(s[0], 0.125f, p0.x));
            float e1 = fexp(fmaf(s[1], 0.125f, p0.y));
            float e2 = fexp(fmaf(s[2], 0.125f, p1.x));
            float e3 = fexp(fmaf(s[3], 0.125f, p1.y));
            sum0 += e0 + e1; sum1 += e2 + e3;
            // stage raw e to smem P tile (coalesced gmem write after the kt loop body)
            int pc = nt * 8 + 2 * tig;
            *(float2*)(Ps + rl0 * 68 + pc) = make_float2(e0, e1);
            *(float2*)(Ps + rl1 * 68 + pc) = make_float2(e2, e3);
            uint32_t h0, l0, h1, l1;
            splitpack(e0, e1, h0, l0);
            splitpack(e2, e3, h1, l1);
            if ((nt & 1) == 0) {
                a01h[0] = h0; a01h[1] = h1; a01l[0] = l0; a01l[1] = l1;
            } else {
                a01h[2] = h0; a01h[3] = h1; a01l[2] = l0; a01l[3] = l1;
                int kc = nt >> 1;
                #pragma unroll
                for (int dtp = 0; dtp < 4; dtp++) {
                    uint32_t vh4[4], vl4[4];
                    ldsm4t(vh4[0], vh4[1], vh4[2], vh4[3], vshb + kc * 2304 + dtp * 32 + loV);
                    ldsm4t(vl4[0], vl4[1], vl4[2], vl4[3], vslb + kc * 2304 + dtp * 32 + loV);
                    hmma(accv[2 * dtp],     a01h, vh4[0], vh4[1]);
                    hmma(accv[2 * dtp],     a01l, vh4[0], vh4[1]);
                    hmma(accv[2 * dtp],     a01h, vl4[0], vl4[1]);
                    hmma(accv[2 * dtp + 1], a01h, vh4[2], vh4[3]);
                    hmma(accv[2 * dtp + 1], a01l, vh4[2], vh4[3]);
                    hmma(accv[2 * dtp + 1], a01h, vl4[2], vl4[3]);
                }
            }
        }
        // coalesced write of this warp's own 16 rows (no cross-warp deps)
        __syncwarp();
        {
            const int c4 = (lane & 15) * 4;
            #pragma unroll
            for (int i = 0; i < 8; i++) {
                int rloc = w * 16 + 2 * i + (lane >> 4);
                float4 v = *(float4*)(Ps + rloc * 68 + c4);
                *(float4*)(attn + ((size_t)bh * S_ + q0 + rloc) * S_ + k0 + c4) = v;
            }
        }
        __syncthreads();
    }
    sum0 += __shfl_xor_sync(0xffffffffu, sum0, 1);
    sum0 += __shfl_xor_sync(0xffffffffu, sum0, 2);
    sum1 += __shfl_xor_sync(0xffffffffu, sum1, 1);
    sum1 += __shfl_xor_sync(0xffffffffu, sum1, 2);
    float inv0 = 1.f / sum0, inv1 = 1.f / sum1;
    if (tig == 0) { rinv[bh * S_ + r0] = inv0; rinv[bh * S_ + r1] = inv1; }
    const int bb = bh >> 3, h = bh & 7;
    #pragma unroll
    for (int dt = 0; dt < 8; dt++) {
        int col = dt * 8 + 2 * tig;
        uint32_t hh, ll;
        splitpack(accv[dt][0] * inv0, accv[dt][1] * inv0, hh, ll);
        *(uint32_t*)(xh + ((size_t)(bb * S_ + r0)) * D_ + h * DK_ + col) = hh;
        *(uint32_t*)(xl + ((size_t)(bb * S_ + r0)) * D_ + h * DK_ + col) = ll;
        splitpack(accv[dt][2] * inv1, accv[dt][3] * inv1, hh, ll);
        *(uint32_t*)(xh + ((size_t)(bb * S_ + r1)) * D_ + h * DK_ + col) = hh;
        *(uint32_t*)(xl + ((size_t)(bb * S_ + r1)) * D_ + h * DK_ + col) = ll;
    }
}

// ---------------- launch ----------------
extern "C" void kernel_launch(void* const* d_in, const int* in_sizes, int n_in,
                              void* d_out, int out_size) {
    const float* q     = (const float*)d_in[0];
    const float* k     = (const float*)d_in[1];
    const float* v     = (const float*)d_in[2];
    const float* pos_k = (const float*)d_in[4];
    const float* ln_w  = (const float*)d_in[5];
    const float* ln_b  = (const float*)d_in[6];
    const float* Wq    = (const float*)d_in[7];
    const float* bq    = (const float*)d_in[8];
    const float* Wk    = (const float*)d_in[9];
    const float* bk    = (const float*)d_in[10];
    const float* Wv    = (const float*)d_in[11];
    const float* bv    = (const float*)d_in[12];
    const float* Wo    = (const float*)d_in[13];
    const float* bo    = (const float*)d_in[14];
    float* out = (float*)d_out;

    uint16_t *xnh, *xnl, *wh, *wl, *phh, *phl, *xh, *xl;
    float *rinv, *attn;
    cudaGetSymbolAddress((void**)&xnh, g_xnh);
    cudaGetSymbolAddress((void**)&xnl, g_xnl);
    cudaGetSymbolAddress((void**)&wh, g_wh);
    cudaGetSymbolAddress((void**)&wl, g_wl);
    cudaGetSymbolAddress((void**)&phh, g_phh);
    cudaGetSymbolAddress((void**)&phl, g_phl);
    cudaGetSymbolAddress((void**)&xh, g_xh);
    cudaGetSymbolAddress((void**)&xl, g_xl);
    cudaGetSymbolAddress((void**)&rinv, g_rinv);
    if ((size_t)out_size >= OUT_ELEMS + ATTN_ELEMS) {
        attn = out + OUT_ELEMS;
    } else {
        cudaGetSymbolAddress((void**)&attn, g_attn_scratch);
    }

    cudaFuncSetAttribute(gemm_mma, cudaFuncAttributeMaxDynamicSharedMemorySize, 81920);
    cudaFuncSetAttribute(attn_mma, cudaFuncAttributeMaxDynamicSharedMemorySize, 108544);

    ln_split<<<dim3(TOK_, 3), 128>>>(q, k, v, ln_w, ln_b, xnh, xnl);
    wsplit<<<dim3(512, 4), 128>>>(Wq, Wk, Wv, Wo, wh, wl);

    const size_t WO = 512ull * 512ull;
    gemm_mma<<<dim3(4, 64, 3), 256, 81920>>>(xnh, xnl, wh, wl, bq, bk, bv,
                                             phh, phl, nullptr, 1, nullptr, nullptr);
    attn_mma<<<dim3(16, 32), 256, 108544>>>(phh, phl, pos_k, attn, rinv, xh, xl);
    gemm_mma<<<dim3(4, 64, 2), 256, 81920>>>(xh, xl, wh + 3 * WO, wl + 3 * WO,
                                             bo, bo, bo, nullptr, nullptr, out, 0,
                                             attn, rinv);
}

// round 14
// speedup vs baseline: 1.0105x; 1.0105x over previous
#include <cuda_runtime.h>
#include <cuda_bf16.h>
#include <cstdint>

#define S_ 2048
#define D_ 512
#define H_ 8
#define DK_ 64
#define BH_ 32
#define TOK_ 8192
#define OUT_ELEMS 4194304ull
#define ATTN_ELEMS 134217728ull
#define PO_ 4194304ull

__device__ uint16_t g_xnh[3ull * TOK_ * D_];
__device__ uint16_t g_xnl[3ull * TOK_ * D_];
__device__ uint16_t g_wh[4ull * 512 * 512];
__device__ uint16_t g_wl[4ull * 512 * 512];
__device__ uint16_t g_phh[3ull * PO_];
__device__ uint16_t g_phl[3ull * PO_];
__device__ uint16_t g_xh[(size_t)TOK_ * D_];
__device__ uint16_t g_xl[(size_t)TOK_ * D_];
__device__ float g_rinv[BH_ * S_];
__device__ float g_attn_scratch[ATTN_ELEMS];

__device__ __forceinline__ void hmma(float c[4], const uint32_t a[4], uint32_t b0, uint32_t b1) {
    asm("mma.sync.aligned.m16n8k16.row.col.f32.bf16.bf16.f32 "
        "{%0,%1,%2,%3},{%4,%5,%6,%7},{%8,%9},{%0,%1,%2,%3};"
        : "+f"(c[0]), "+f"(c[1]), "+f"(c[2]), "+f"(c[3])
        : "r"(a[0]), "r"(a[1]), "r"(a[2]), "r"(a[3]), "r"(b0), "r"(b1));
}
__device__ __forceinline__ void ldsm4(uint32_t& r0, uint32_t& r1, uint32_t& r2, uint32_t& r3,
                                      uint32_t addr) {
    asm volatile("ldmatrix.sync.aligned.m8n8.x4.shared.b16 {%0,%1,%2,%3}, [%4];"
                 : "=r"(r0), "=r"(r1), "=r"(r2), "=r"(r3) : "r"(addr));
}
__device__ __forceinline__ void ldsm4t(uint32_t& r0, uint32_t& r1, uint32_t& r2, uint32_t& r3,
                                       uint32_t addr) {
    asm volatile("ldmatrix.sync.aligned.m8n8.x4.trans.shared.b16 {%0,%1,%2,%3}, [%4];"
                 : "=r"(r0), "=r"(r1), "=r"(r2), "=r"(r3) : "r"(addr));
}
__device__ __forceinline__ void cpa16(uint32_t dst, const void* src) {
    asm volatile("cp.async.cg.shared.global [%0], [%1], 16;" :: "r"(dst), "l"(src));
}
#define CP_COMMIT() asm volatile("cp.async.commit_group;")
#define CP_WAIT0()  asm volatile("cp.async.wait_group 0;")
#define CP_WAIT1()  asm volatile("cp.async.wait_group 1;")
__device__ __forceinline__ void splitpack(float f0, float f1, uint32_t& h, uint32_t& l) {
    asm("cvt.rn.bf16x2.f32 %0, %1, %2;" : "=r"(h) : "f"(f1), "f"(f0));
    float g0 = __uint_as_float(h << 16);
    float g1 = __uint_as_float(h & 0xffff0000u);
    asm("cvt.rn.bf16x2.f32 %0, %1, %2;" : "=r"(l) : "f"(f1 - g1), "f"(f0 - g0));
}
__device__ __forceinline__ float fexp(float x) {
    float t = x * 1.4426950408889634f;
    t = fmaxf(t, -126.0f);
    float z = t + 12582912.0f;
    int   n = (__float_as_int(z) & 0x7FFFFF) - 0x400000;
    float f = t - (z - 12582912.0f);
    float p = 1.5403530e-4f;
    p = fmaf(p, f, 1.3333558e-3f);
    p = fmaf(p, f, 9.6181291e-3f);
    p = fmaf(p, f, 5.5504109e-2f);
    p = fmaf(p, f, 2.4022651e-1f);
    p = fmaf(p, f, 6.9314718e-1f);
    p = fmaf(p, f, 1.0f);
    return __int_as_float(__float_as_int(p) + (n << 23));
}

// ---------------- K1: LayerNorm -> split bf16 ----------------
__global__ void ln_split(const float* __restrict__ q, const float* __restrict__ k,
                         const float* __restrict__ v, const float* __restrict__ w,
                         const float* __restrict__ b,
                         uint16_t* __restrict__ xh, uint16_t* __restrict__ xl) {
    const int row = blockIdx.x, which = blockIdx.y, tid = threadIdx.x;
    const float* src = (which == 0) ? q : (which == 1) ? k : v;
    float4 x = *(const float4*)(src + (size_t)row * D_ + tid * 4);
    float s  = x.x + x.y + x.z + x.w;
    float ss = x.x * x.x + x.y * x.y + x.z * x.z + x.w * x.w;
    __shared__ float red[2][4];
    #pragma unroll
    for (int o = 16; o; o >>= 1) {
        s  += __shfl_xor_sync(0xffffffffu, s, o);
        ss += __shfl_xor_sync(0xffffffffu, ss, o);
    }
    if ((tid & 31) == 0) { red[0][tid >> 5] = s; red[1][tid >> 5] = ss; }
    __syncthreads();
    s  = red[0][0] + red[0][1] + red[0][2] + red[0][3];
    ss = red[1][0] + red[1][1] + red[1][2] + red[1][3];
    const float mu  = s * (1.0f / D_);
    const float var = ss * (1.0f / D_) - mu * mu;
    const float r   = rsqrtf(var + 1e-5f);
    float4 wv = *(const float4*)(w + tid * 4);
    float4 bv = *(const float4*)(b + tid * 4);
    float o0 = (x.x - mu) * r * wv.x + bv.x;
    float o1 = (x.y - mu) * r * wv.y + bv.y;
    float o2 = (x.z - mu) * r * wv.z + bv.z;
    float o3 = (x.w - mu) * r * wv.w + bv.w;
    uint32_t h01, l01, h23, l23;
    splitpack(o0, o1, h01, l01); splitpack(o2, o3, h23, l23);
    size_t base = ((size_t)which * TOK_ + row) * D_ + tid * 4;
    *(uint32_t*)(xh + base) = h01; *(uint32_t*)(xh + base + 2) = h23;
    *(uint32_t*)(xl + base) = l01; *(uint32_t*)(xl + base + 2) = l23;
}

// ---------------- K2: split weights ----------------
__global__ void wsplit(const float* __restrict__ Wq, const float* __restrict__ Wk,
                       const float* __restrict__ Wv, const float* __restrict__ Wo,
                       uint16_t* __restrict__ wh, uint16_t* __restrict__ wl) {
    const int row = blockIdx.x, mat = blockIdx.y, tid = threadIdx.x;
    const float* W = (mat == 0) ? Wq : (mat == 1) ? Wk : (mat == 2) ? Wv : Wo;
    float4 x = *(const float4*)(W + (size_t)row * 512 + tid * 4);
    uint32_t h01, l01, h23, l23;
    splitpack(x.x, x.y, h01, l01); splitpack(x.z, x.w, h23, l23);
    size_t base = ((size_t)mat * 512 + row) * 512 + tid * 4;
    *(uint32_t*)(wh + base) = h01; *(uint32_t*)(wh + base + 2) = h23;
    *(uint32_t*)(wl + base) = l01; *(uint32_t*)(wl + base + 2) = l23;
}

// ---------------- K3: batched projections / K5: out-proj + parallel rescale ----------------
__global__ __launch_bounds__(256, 2)
void gemm_mma(const uint16_t* __restrict__ Ab, const uint16_t* __restrict__ Alb,
              const uint16_t* __restrict__ Bb, const uint16_t* __restrict__ Blb,
              const float* __restrict__ b0p, const float* __restrict__ b1p,
              const float* __restrict__ b2p,
              uint16_t* __restrict__ Dh, uint16_t* __restrict__ Dl,
              float* __restrict__ Df, int mode,
              float* __restrict__ attn, const float* __restrict__ rinvp) {
    extern __shared__ uint16_t sm[];
    const int tid = threadIdx.x;
    if (mode == 0 && blockIdx.z == 1) {
        int linear = blockIdx.y * 4 + blockIdx.x;
        int bh = linear >> 3, r0 = (linear & 7) * 256;
        for (int row = 0; row < 256; row++) {
            float inv = rinvp[bh * S_ + r0 + row];
            float4* p = (float4*)(attn + ((size_t)bh * S_ + r0 + row) * S_);
            float4 a = p[tid], b = p[tid + 256];
            a.x *= inv; a.y *= inv; a.z *= inv; a.w *= inv;
            b.x *= inv; b.y *= inv; b.z *= inv; b.w *= inv;
            p[tid] = a; p[tid + 256] = b;
        }
        return;
    }
    const int w = tid >> 5, lane = tid & 31;
    const int gid = lane >> 2, tig = lane & 3;
    const int n0 = blockIdx.x * 128, m0 = blockIdx.y * 128;
    const int mz = (mode == 1) ? blockIdx.z : 0;
    const uint16_t* Ah = Ab  + (size_t)mz * TOK_ * D_;
    const uint16_t* Al = Alb + (size_t)mz * TOK_ * D_;
    const uint16_t* Bh = Bb  + (size_t)mz * 512 * 512;
    const uint16_t* Bl = Blb + (size_t)mz * 512 * 512;
    const float* bias = (mz == 0) ? b0p : (mz == 1) ? b1p : b2p;
    const int wm = w >> 2, wn = w & 3;
    const uint32_t sbase = (uint32_t)__cvta_generic_to_shared(sm);
    const int srow = tid >> 1;
    const uint32_t soff = (uint32_t)(srow * 80 + (tid & 1) * 32);
    const size_t goff = (size_t)srow * 512 + (tid & 1) * 16;

    float acc[4][4][4];
    #pragma unroll
    for (int i = 0; i < 4; i++)
        #pragma unroll
        for (int j = 0; j < 4; j++)
            #pragma unroll
            for (int kq = 0; kq < 4; kq++) acc[i][j][kq] = 0.f;

    {
        uint32_t b = sbase;
        cpa16(b + soff,          Ah + (size_t)m0 * 512 + goff);
        cpa16(b + soff + 16,     Ah + (size_t)m0 * 512 + goff + 8);
        cpa16(b + 10240 + soff,      Al + (size_t)m0 * 512 + goff);
        cpa16(b + 10240 + soff + 16, Al + (size_t)m0 * 512 + goff + 8);
        cpa16(b + 20480 + soff,      Bh + (size_t)n0 * 512 + goff);
        cpa16(b + 20480 + soff + 16, Bh + (size_t)n0 * 512 + goff + 8);
        cpa16(b + 30720 + soff,      Bl + (size_t)n0 * 512 + goff);
        cpa16(b + 30720 + soff + 16, Bl + (size_t)n0 * 512 + goff + 8);
        CP_COMMIT();
    }
    for (int c = 0; c < 16; c++) {
        if (c + 1 < 16) {
            uint32_t b = sbase + ((c + 1) & 1) * 40960;
            size_t g = goff + (c + 1) * 32;
            cpa16(b + soff,          Ah + (size_t)m0 * 512 + g);
            cpa16(b + soff + 16,     Ah + (size_t)m0 * 512 + g + 8);
            cpa16(b + 10240 + soff,      Al + (size_t)m0 * 512 + g);
            cpa16(b + 10240 + soff + 16, Al + (size_t)m0 * 512 + g + 8);
            cpa16(b + 20480 + soff,      Bh + (size_t)n0 * 512 + g);
            cpa16(b + 20480 + soff + 16, Bh + (size_t)n0 * 512 + g + 8);
            cpa16(b + 30720 + soff,      Bl + (size_t)n0 * 512 + g);
            cpa16(b + 30720 + soff + 16, Bl + (size_t)n0 * 512 + g + 8);
            CP_COMMIT();
            CP_WAIT1();
        } else {
            CP_WAIT0();
        }
        __syncthreads();
        const uint16_t* sAh = sm + (size_t)(c & 1) * 20480;
        const uint16_t* sAl = sAh + 5120;
        const uint16_t* sBh = sAh + 10240;
        const uint16_t* sBl = sAh + 15360;
        #pragma unroll
        for (int ks = 0; ks < 2; ks++) {
            const int dk = ks * 16 + 2 * tig;
            uint32_t ah[4][4], al[4][4], bhf[4][2], blf[4][2];
            #pragma unroll
            for (int mt = 0; mt < 4; mt++) {
                int ar = wm * 64 + mt * 16 + gid;
                ah[mt][0] = *(const uint32_t*)(sAh + ar * 40 + dk);
                ah[mt][1] = *(const uint32_t*)(sAh + (ar + 8) * 40 + dk);
                ah[mt][2] = *(const uint32_t*)(sAh + ar * 40 + dk + 8);
                ah[mt][3] = *(const uint32_t*)(sAh + (ar + 8) * 40 + dk + 8);
                al[mt][0] = *(const uint32_t*)(sAl + ar * 40 + dk);
                al[mt][1] = *(const uint32_t*)(sAl + (ar + 8) * 40 + dk);
                al[mt][2] = *(const uint32_t*)(sAl + ar * 40 + dk + 8);
                al[mt][3] = *(const uint32_t*)(sAl + (ar + 8) * 40 + dk + 8);
            }
            #pragma unroll
            for (int nt = 0; nt < 4; nt++) {
                int br = wn * 32 + nt * 8 + gid;
                bhf[nt][0] = *(const uint32_t*)(sBh + br * 40 + dk);
                bhf[nt][1] = *(const uint32_t*)(sBh + br * 40 + dk + 8);
                blf[nt][0] = *(const uint32_t*)(sBl + br * 40 + dk);
                blf[nt][1] = *(const uint32_t*)(sBl + br * 40 + dk + 8);
            }
            #pragma unroll
            for (int mt = 0; mt < 4; mt++)
                #pragma unroll
                for (int nt = 0; nt < 4; nt++) {
                    hmma(acc[mt][nt], ah[mt], bhf[nt][0], bhf[nt][1]);
                    hmma(acc[mt][nt], al[mt], bhf[nt][0], bhf[nt][1]);
                    hmma(acc[mt][nt], ah[mt], blf[nt][0], blf[nt][1]);
                }
        }
        __syncthreads();
    }
    #pragma unroll
    for (int mt = 0; mt < 4; mt++) {
        int row0 = m0 + wm * 64 + mt * 16 + gid, row1 = row0 + 8;
        #pragma unroll
        for (int nt = 0; nt < 4; nt++) {
            int nc = n0 + wn * 32 + nt * 8 + 2 * tig;
            float b0 = bias[nc], b1 = bias[nc + 1];
            float c00 = acc[mt][nt][0] + b0, c01 = acc[mt][nt][1] + b1;
            float c10 = acc[mt][nt][2] + b0, c11 = acc[mt][nt][3] + b1;
            if (mode == 0) {
                *(float2*)(Df + (size_t)row0 * 512 + nc) = make_float2(c00, c01);
                *(float2*)(Df + (size_t)row1 * 512 + nc) = make_float2(c10, c11);
            } else {
                int h = nc >> 6, dd = nc & 63;
                uint32_t hh, ll;
                int bb = row0 >> 11, tk = row0 & 2047;
                size_t o = ((size_t)mz * PO_) + (((size_t)(bb * H_ + h)) * S_ + tk) * DK_ + dd;
                splitpack(c00, c01, hh, ll);
                *(uint32_t*)(Dh + o) = hh; *(uint32_t*)(Dl + o) = ll;
                bb = row1 >> 11; tk = row1 & 2047;
                o = ((size_t)mz * PO_) + (((size_t)(bb * H_ + h)) * S_ + tk) * DK_ + dd;
                splitpack(c10, c11, hh, ll);
                *(uint32_t*)(Dh + o) = hh; *(uint32_t*)(Dl + o) = ll;
            }
        }
    }
}

// ---------------- K4: fused attention, dual-chain QK ----------------
__global__ __launch_bounds__(256, 2)
void attn_mma(const uint16_t* __restrict__ ph, const uint16_t* __restrict__ pl,
              const float* __restrict__ pos, float* __restrict__ attn,
              float* __restrict__ rinv,
              uint16_t* __restrict__ xh, uint16_t* __restrict__ xl) {
    extern __shared__ uint16_t sm[];
    uint16_t* QH  = sm;
    uint16_t* QL  = sm + 9216;
    const int tid = threadIdx.x, w = tid >> 5, lane = tid & 31;
    const int gid = lane >> 2, tig = lane & 3;
    const int qt = blockIdx.x, bh = blockIdx.y, q0 = qt * 128;
    const uint16_t* qg  = ph;
    const uint16_t* qgl = pl;
    const uint16_t* kg  = ph + PO_;
    const uint16_t* kgl = pl + PO_;
    const uint16_t* vg  = ph + 2 * PO_;
    const uint16_t* vgl = pl + 2 * PO_;

    const uint32_t sbase = (uint32_t)__cvta_generic_to_shared(sm);
    const uint32_t loK = (lane & 7) * 144 + (lane >> 3) * 16;
    const uint32_t loV = (lane & 15) * 144 + (lane >> 4) * 16;
    const int vrow = tid >> 2;
    const uint32_t voff = (uint32_t)(vrow * 144 + (tid & 3) * 32);
    const size_t vgoff = (size_t)(tid & 3) * 16;

    {
        int row = tid >> 1, half = (tid & 1) * 32;
        const uint4* s1 = (const uint4*)(qg  + ((size_t)bh * S_ + q0 + row) * DK_ + half);
        const uint4* s2 = (const uint4*)(qgl + ((size_t)bh * S_ + q0 + row) * DK_ + half);
        uint4* d1 = (uint4*)(QH + row * 72 + half);
        uint4* d2 = (uint4*)(QL + row * 72 + half);
        #pragma unroll
        for (int j = 0; j < 4; j++) { d1[j] = s1[j]; d2[j] = s2[j]; }
    }
    __syncthreads();
    uint32_t qfh[4][4], qfl[4][4];
    {
        int qr = w * 16 + gid;
        #pragma unroll
        for (int ks = 0; ks < 4; ks++) {
            int dc = ks * 16 + 2 * tig;
            qfh[ks][0] = *(const uint32_t*)(QH + qr * 72 + dc);
            qfh[ks][1] = *(const uint32_t*)(QH + (qr + 8) * 72 + dc);
            qfh[ks][2] = *(const uint32_t*)(QH + qr * 72 + dc + 8);
            qfh[ks][3] = *(const uint32_t*)(QH + (qr + 8) * 72 + dc + 8);
            qfl[ks][0] = *(const uint32_t*)(QL + qr * 72 + dc);
            qfl[ks][1] = *(const uint32_t*)(QL + (qr + 8) * 72 + dc);
            qfl[ks][2] = *(const uint32_t*)(QL + qr * 72 + dc + 8);
            qfl[ks][3] = *(const uint32_t*)(QL + (qr + 8) * 72 + dc + 8);
        }
    }
    __syncthreads();

    const int r0 = q0 + w * 16 + gid, r1 = r0 + 8;
    float sum0 = 0.f, sum1 = 0.f;
    float accv[8][4];
    #pragma unroll
    for (int i = 0; i < 8; i++)
        #pragma unroll
        for (int j = 0; j < 4; j++) accv[i][j] = 0.f;
    uint32_t a01h[4], a01l[4];

    {
        size_t g = ((size_t)bh * S_ + vrow) * DK_ + vgoff;
        uint32_t b = sbase;
        cpa16(b + voff,              kg + g);
        cpa16(b + voff + 16,         kg + g + 8);
        cpa16(b + 9216 + voff,       kgl + g);
        cpa16(b + 9216 + voff + 16,  kgl + g + 8);
        cpa16(b + 18432 + voff,      vg + g);
        cpa16(b + 18432 + voff + 16, vg + g + 8);
        cpa16(b + 27648 + voff,      vgl + g);
        cpa16(b + 27648 + voff + 16, vgl + g + 8);
        CP_COMMIT();
    }
    for (int kt = 0; kt < 32; kt++) {
        const int k0 = kt * 64;
        if (kt + 1 < 32) {
            size_t g = ((size_t)bh * S_ + (kt + 1) * 64 + vrow) * DK_ + vgoff;
            uint32_t b = sbase + ((kt + 1) & 1) * 36864;
            cpa16(b + voff,              kg + g);
            cpa16(b + voff + 16,         kg + g + 8);
            cpa16(b + 9216 + voff,       kgl + g);
            cpa16(b + 9216 + voff + 16,  kgl + g + 8);
            cpa16(b + 18432 + voff,      vg + g);
            cpa16(b + 18432 + voff + 16, vg + g + 8);
            cpa16(b + 27648 + voff,      vgl + g);
            cpa16(b + 27648 + voff + 16, vgl + g + 8);
            CP_COMMIT();
            CP_WAIT1();
        } else {
            CP_WAIT0();
        }
        __syncthreads();
        const uint32_t bb0 = sbase + (kt & 1) * 36864;
        const uint32_t khb = bb0, klb = bb0 + 9216;
        const uint32_t vshb = bb0 + 18432, vslb = bb0 + 27648;

        #pragma unroll
        for (int nt = 0; nt < 8; nt++) {
            float sa[4] = {0.f, 0.f, 0.f, 0.f};
            float sb[4] = {0.f, 0.f, 0.f, 0.f};
            uint32_t kb[8], klo[8];
            ldsm4(kb[0], kb[1], kb[2], kb[3], khb + nt * 1152 + loK);
            ldsm4(kb[4], kb[5], kb[6], kb[7], khb + nt * 1152 + 64 + loK);
            ldsm4(klo[0], klo[1], klo[2], klo[3], klb + nt * 1152 + loK);
            ldsm4(klo[4], klo[5], klo[6], klo[7], klb + nt * 1152 + 64 + loK);
            // two independent accumulation chains (ks 0-1 -> sa, ks 2-3 -> sb)
            #pragma unroll
            for (int ks = 0; ks < 2; ks++) {
                hmma(sa, qfh[ks], kb[2 * ks], kb[2 * ks + 1]);
                hmma(sb, qfh[ks + 2], kb[2 * ks + 4], kb[2 * ks + 5]);
                hmma(sa, qfl[ks], kb[2 * ks], kb[2 * ks + 1]);
                hmma(sb, qfl[ks + 2], kb[2 * ks + 4], kb[2 * ks + 5]);
                hmma(sa, qfh[ks], klo[2 * ks], klo[2 * ks + 1]);
                hmma(sb, qfh[ks + 2], klo[2 * ks + 4], klo[2 * ks + 5]);
            }
            float s0v = sa[0] + sb[0];
            float s1v = sa[1] + sb[1];
            float s2v = sa[2] + sb[2];
            float s3v = sa[3] + sb[3];
            int col = k0 + nt * 8 + 2 * tig;
            float2 p0 = *(const float2*)(pos + (size_t)r0 * S_ + col);
            float2 p1 = *(const float2*)(pos + (size_t)r1 * S_ + col);
            float e0 = fexp(fmaf(s0v, 0.125f, p0.x));
            float e1 = fexp(fmaf(s1v, 0.125f, p0.y));
            float e2 = fexp(fmaf(s2v, 0.125f, p1.x));
            float e3 = fexp(fmaf(s3v, 0.125f, p1.y));
            sum0 += e0 + e1; sum1 += e2 + e3;
            *(float2*)(attn + ((size_t)bh * S_ + r0) * S_ + col) = make_float2(e0, e1);
            *(float2*)(attn + ((size_t)bh * S_ + r1) * S_ + col) = make_float2(e2, e3);
            uint32_t h0, l0, h1, l1;
            splitpack(e0, e1, h0, l0);
            splitpack(e2, e3, h1, l1);
            if ((nt & 1) == 0) {
                a01h[0] = h0; a01h[1] = h1; a01l[0] = l0; a01l[1] = l1;
            } else {
                a01h[2] = h0; a01h[3] = h1; a01l[2] = l0; a01l[3] = l1;
                int kc = nt >> 1;
                #pragma unroll
                for (int dtp = 0; dtp < 4; dtp++) {
                    uint32_t vh4[4], vl4[4];
                    ldsm4t(vh4[0], vh4[1], vh4[2], vh4[3], vshb + kc * 2304 + dtp * 32 + loV);
                    ldsm4t(vl4[0], vl4[1], vl4[2], vl4[3], vslb + kc * 2304 + dtp * 32 + loV);
                    hmma(accv[2 * dtp],     a01h, vh4[0], vh4[1]);
                    hmma(accv[2 * dtp],     a01l, vh4[0], vh4[1]);
                    hmma(accv[2 * dtp],     a01h, vl4[0], vl4[1]);
                    hmma(accv[2 * dtp + 1], a01h, vh4[2], vh4[3]);
                    hmma(accv[2 * dtp + 1], a01l, vh4[2], vh4[3]);
                    hmma(accv[2 * dtp + 1], a01h, vl4[2], vl4[3]);
                }
            }
        }
        __syncthreads();
    }
    sum0 += __shfl_xor_sync(0xffffffffu, sum0, 1);
    sum0 += __shfl_xor_sync(0xffffffffu, sum0, 2);
    sum1 += __shfl_xor_sync(0xffffffffu, sum1, 1);
    sum1 += __shfl_xor_sync(0xffffffffu, sum1, 2);
    float inv0 = 1.f / sum0, inv1 = 1.f / sum1;
    if (tig == 0) { rinv[bh * S_ + r0] = inv0; rinv[bh * S_ + r1] = inv1; }
    const int bb = bh >> 3, h = bh & 7;
    #pragma unroll
    for (int dt = 0; dt < 8; dt++) {
        int col = dt * 8 + 2 * tig;
        uint32_t hh, ll;
        splitpack(accv[dt][0] * inv0, accv[dt][1] * inv0, hh, ll);
        *(uint32_t*)(xh + ((size_t)(bb * S_ + r0)) * D_ + h * DK_ + col) = hh;
        *(uint32_t*)(xl + ((size_t)(bb * S_ + r0)) * D_ + h * DK_ + col) = ll;
        splitpack(accv[dt][2] * inv1, accv[dt][3] * inv1, hh, ll);
        *(uint32_t*)(xh + ((size_t)(bb * S_ + r1)) * D_ + h * DK_ + col) = hh;
        *(uint32_t*)(xl + ((size_t)(bb * S_ + r1)) * D_ + h * DK_ + col) = ll;
    }
}

// ---------------- launch ----------------
extern "C" void kernel_launch(void* const* d_in, const int* in_sizes, int n_in,
                              void* d_out, int out_size) {
    const float* q     = (const float*)d_in[0];
    const float* k     = (const float*)d_in[1];
    const float* v     = (const float*)d_in[2];
    const float* pos_k = (const float*)d_in[4];
    const float* ln_w  = (const float*)d_in[5];
    const float* ln_b  = (const float*)d_in[6];
    const float* Wq    = (const float*)d_in[7];
    const float* bq    = (const float*)d_in[8];
    const float* Wk    = (const float*)d_in[9];
    const float* bk    = (const float*)d_in[10];
    const float* Wv    = (const float*)d_in[11];
    const float* bv    = (const float*)d_in[12];
    const float* Wo    = (const float*)d_in[13];
    const float* bo    = (const float*)d_in[14];
    float* out = (float*)d_out;

    uint16_t *xnh, *xnl, *wh, *wl, *phh, *phl, *xh, *xl;
    float *rinv, *attn;
    cudaGetSymbolAddress((void**)&xnh, g_xnh);
    cudaGetSymbolAddress((void**)&xnl, g_xnl);
    cudaGetSymbolAddress((void**)&wh, g_wh);
    cudaGetSymbolAddress((void**)&wl, g_wl);
    cudaGetSymbolAddress((void**)&phh, g_phh);
    cudaGetSymbolAddress((void**)&phl, g_phl);
    cudaGetSymbolAddress((void**)&xh, g_xh);
    cudaGetSymbolAddress((void**)&xl, g_xl);
    cudaGetSymbolAddress((void**)&rinv, g_rinv);
    if ((size_t)out_size >= OUT_ELEMS + ATTN_ELEMS) {
        attn = out + OUT_ELEMS;
    } else {
        cudaGetSymbolAddress((void**)&attn, g_attn_scratch);
    }

    cudaFuncSetAttribute(gemm_mma, cudaFuncAttributeMaxDynamicSharedMemorySize, 81920);
    cudaFuncSetAttribute(attn_mma, cudaFuncAttributeMaxDynamicSharedMemorySize, 73728);

    ln_split<<<dim3(TOK_, 3), 128>>>(q, k, v, ln_w, ln_b, xnh, xnl);
    wsplit<<<dim3(512, 4), 128>>>(Wq, Wk, Wv, Wo, wh, wl);

    const size_t WO = 512ull * 512ull;
    gemm_mma<<<dim3(4, 64, 3), 256, 81920>>>(xnh, xnl, wh, wl, bq, bk, bv,
                                             phh, phl, nullptr, 1, nullptr, nullptr);
    attn_mma<<<dim3(16, 32), 256, 73728>>>(phh, phl, pos_k, attn, rinv, xh, xl);
    gemm_mma<<<dim3(4, 64, 2), 256, 81920>>>(xh, xl, wh + 3 * WO, wl + 3 * WO,
                                             bo, bo, bo, nullptr, nullptr, out, 0,
                                             attn, rinv);
}

// round 15
// speedup vs baseline: 1.0213x; 1.0107x over previous
#include <cuda_runtime.h>
#include <cuda_bf16.h>
#include <cstdint>

#define S_ 2048
#define D_ 512
#define H_ 8
#define DK_ 64
#define BH_ 32
#define TOK_ 8192
#define OUT_ELEMS 4194304ull
#define ATTN_ELEMS 134217728ull
#define PO_ 4194304ull

__device__ uint16_t g_xnh[3ull * TOK_ * D_];
__device__ uint16_t g_xnl[3ull * TOK_ * D_];
__device__ uint16_t g_wh[4ull * 512 * 512];
__device__ uint16_t g_wl[4ull * 512 * 512];
__device__ uint16_t g_phh[3ull * PO_];
__device__ uint16_t g_phl[3ull * PO_];
__device__ uint16_t g_xh[(size_t)TOK_ * D_];
__device__ uint16_t g_xl[(size_t)TOK_ * D_];
__device__ float g_rinv[BH_ * S_];
__device__ float g_attn_scratch[ATTN_ELEMS];

__device__ __forceinline__ void hmma(float c[4], const uint32_t a[4], uint32_t b0, uint32_t b1) {
    asm("mma.sync.aligned.m16n8k16.row.col.f32.bf16.bf16.f32 "
        "{%0,%1,%2,%3},{%4,%5,%6,%7},{%8,%9},{%0,%1,%2,%3};"
        : "+f"(c[0]), "+f"(c[1]), "+f"(c[2]), "+f"(c[3])
        : "r"(a[0]), "r"(a[1]), "r"(a[2]), "r"(a[3]), "r"(b0), "r"(b1));
}
__device__ __forceinline__ void ldsm4(uint32_t& r0, uint32_t& r1, uint32_t& r2, uint32_t& r3,
                                      uint32_t addr) {
    asm volatile("ldmatrix.sync.aligned.m8n8.x4.shared.b16 {%0,%1,%2,%3}, [%4];"
                 : "=r"(r0), "=r"(r1), "=r"(r2), "=r"(r3) : "r"(addr));
}
__device__ __forceinline__ void ldsm4t(uint32_t& r0, uint32_t& r1, uint32_t& r2, uint32_t& r3,
                                       uint32_t addr) {
    asm volatile("ldmatrix.sync.aligned.m8n8.x4.trans.shared.b16 {%0,%1,%2,%3}, [%4];"
                 : "=r"(r0), "=r"(r1), "=r"(r2), "=r"(r3) : "r"(addr));
}
__device__ __forceinline__ void cpa16(uint32_t dst, const void* src) {
    asm volatile("cp.async.cg.shared.global [%0], [%1], 16;" :: "r"(dst), "l"(src));
}
#define CP_COMMIT() asm volatile("cp.async.commit_group;")
#define CP_WAIT0()  asm volatile("cp.async.wait_group 0;")
#define CP_WAIT1()  asm volatile("cp.async.wait_group 1;")
__device__ __forceinline__ void splitpack(float f0, float f1, uint32_t& h, uint32_t& l) {
    asm("cvt.rn.bf16x2.f32 %0, %1, %2;" : "=r"(h) : "f"(f1), "f"(f0));
    float g0 = __uint_as_float(h << 16);
    float g1 = __uint_as_float(h & 0xffff0000u);
    asm("cvt.rn.bf16x2.f32 %0, %1, %2;" : "=r"(l) : "f"(f1 - g1), "f"(f0 - g0));
}
__device__ __forceinline__ float fexp(float x) {
    float t = x * 1.4426950408889634f;
    t = fmaxf(t, -126.0f);
    float z = t + 12582912.0f;
    int   n = (__float_as_int(z) & 0x7FFFFF) - 0x400000;
    float f = t - (z - 12582912.0f);
    float p = 1.5403530e-4f;
    p = fmaf(p, f, 1.3333558e-3f);
    p = fmaf(p, f, 9.6181291e-3f);
    p = fmaf(p, f, 5.5504109e-2f);
    p = fmaf(p, f, 2.4022651e-1f);
    p = fmaf(p, f, 6.9314718e-1f);
    p = fmaf(p, f, 1.0f);
    return __int_as_float(__float_as_int(p) + (n << 23));
}

// ---------------- K1: LayerNorm -> split bf16 ----------------
__global__ void ln_split(const float* __restrict__ q, const float* __restrict__ k,
                         const float* __restrict__ v, const float* __restrict__ w,
                         const float* __restrict__ b,
                         uint16_t* __restrict__ xh, uint16_t* __restrict__ xl) {
    const int row = blockIdx.x, which = blockIdx.y, tid = threadIdx.x;
    const float* src = (which == 0) ? q : (which == 1) ? k : v;
    float4 x = *(const float4*)(src + (size_t)row * D_ + tid * 4);
    float s  = x.x + x.y + x.z + x.w;
    float ss = x.x * x.x + x.y * x.y + x.z * x.z + x.w * x.w;
    __shared__ float red[2][4];
    #pragma unroll
    for (int o = 16; o; o >>= 1) {
        s  += __shfl_xor_sync(0xffffffffu, s, o);
        ss += __shfl_xor_sync(0xffffffffu, ss, o);
    }
    if ((tid & 31) == 0) { red[0][tid >> 5] = s; red[1][tid >> 5] = ss; }
    __syncthreads();
    s  = red[0][0] + red[0][1] + red[0][2] + red[0][3];
    ss = red[1][0] + red[1][1] + red[1][2] + red[1][3];
    const float mu  = s * (1.0f / D_);
    const float var = ss * (1.0f / D_) - mu * mu;
    const float r   = rsqrtf(var + 1e-5f);
    float4 wv = *(const float4*)(w + tid * 4);
    float4 bv = *(const float4*)(b + tid * 4);
    float o0 = (x.x - mu) * r * wv.x + bv.x;
    float o1 = (x.y - mu) * r * wv.y + bv.y;
    float o2 = (x.z - mu) * r * wv.z + bv.z;
    float o3 = (x.w - mu) * r * wv.w + bv.w;
    uint32_t h01, l01, h23, l23;
    splitpack(o0, o1, h01, l01); splitpack(o2, o3, h23, l23);
    size_t base = ((size_t)which * TOK_ + row) * D_ + tid * 4;
    *(uint32_t*)(xh + base) = h01; *(uint32_t*)(xh + base + 2) = h23;
    *(uint32_t*)(xl + base) = l01; *(uint32_t*)(xl + base + 2) = l23;
}

// ---------------- K2: split weights ----------------
__global__ void wsplit(const float* __restrict__ Wq, const float* __restrict__ Wk,
                       const float* __restrict__ Wv, const float* __restrict__ Wo,
                       uint16_t* __restrict__ wh, uint16_t* __restrict__ wl) {
    const int row = blockIdx.x, mat = blockIdx.y, tid = threadIdx.x;
    const float* W = (mat == 0) ? Wq : (mat == 1) ? Wk : (mat == 2) ? Wv : Wo;
    float4 x = *(const float4*)(W + (size_t)row * 512 + tid * 4);
    uint32_t h01, l01, h23, l23;
    splitpack(x.x, x.y, h01, l01); splitpack(x.z, x.w, h23, l23);
    size_t base = ((size_t)mat * 512 + row) * 512 + tid * 4;
    *(uint32_t*)(wh + base) = h01; *(uint32_t*)(wh + base + 2) = h23;
    *(uint32_t*)(wl + base) = l01; *(uint32_t*)(wl + base + 2) = l23;
}

// ---------------- K3: batched projections / K5: out-proj + parallel rescale ----------------
__global__ __launch_bounds__(256, 2)
void gemm_mma(const uint16_t* __restrict__ Ab, const uint16_t* __restrict__ Alb,
              const uint16_t* __restrict__ Bb, const uint16_t* __restrict__ Blb,
              const float* __restrict__ b0p, const float* __restrict__ b1p,
              const float* __restrict__ b2p,
              uint16_t* __restrict__ Dh, uint16_t* __restrict__ Dl,
              float* __restrict__ Df, int mode,
              float* __restrict__ attn, const float* __restrict__ rinvp) {
    extern __shared__ uint16_t sm[];
    const int tid = threadIdx.x;
    if (mode == 0 && blockIdx.z >= 1) {
        // rescale: 512 blocks, 128 rows each, 4-row batches for MLP
        int rid = (blockIdx.z - 1) * 256 + blockIdx.y * 4 + blockIdx.x;  // 0..511
        int bh = rid >> 4, r0 = (rid & 15) * 128;
        for (int rg = 0; rg < 32; rg++) {
            int br = r0 + rg * 4;
            float inv0 = rinvp[bh * S_ + br];
            float inv1 = rinvp[bh * S_ + br + 1];
            float inv2 = rinvp[bh * S_ + br + 2];
            float inv3 = rinvp[bh * S_ + br + 3];
            float4* p0 = (float4*)(attn + ((size_t)bh * S_ + br) * S_);
            float4* p1 = (float4*)(attn + ((size_t)bh * S_ + br + 1) * S_);
            float4* p2 = (float4*)(attn + ((size_t)bh * S_ + br + 2) * S_);
            float4* p3 = (float4*)(attn + ((size_t)bh * S_ + br + 3) * S_);
            float4 a0 = p0[tid], b0 = p0[tid + 256];
            float4 a1 = p1[tid], b1 = p1[tid + 256];
            float4 a2 = p2[tid], b2 = p2[tid + 256];
            float4 a3 = p3[tid], b3 = p3[tid + 256];
            a0.x *= inv0; a0.y *= inv0; a0.z *= inv0; a0.w *= inv0;
            b0.x *= inv0; b0.y *= inv0; b0.z *= inv0; b0.w *= inv0;
            a1.x *= inv1; a1.y *= inv1; a1.z *= inv1; a1.w *= inv1;
            b1.x *= inv1; b1.y *= inv1; b1.z *= inv1; b1.w *= inv1;
            a2.x *= inv2; a2.y *= inv2; a2.z *= inv2; a2.w *= inv2;
            b2.x *= inv2; b2.y *= inv2; b2.z *= inv2; b2.w *= inv2;
            a3.x *= inv3; a3.y *= inv3; a3.z *= inv3; a3.w *= inv3;
            b3.x *= inv3; b3.y *= inv3; b3.z *= inv3; b3.w *= inv3;
            p0[tid] = a0; p0[tid + 256] = b0;
            p1[tid] = a1; p1[tid + 256] = b1;
            p2[tid] = a2; p2[tid + 256] = b2;
            p3[tid] = a3; p3[tid + 256] = b3;
        }
        return;
    }
    const int w = tid >> 5, lane = tid & 31;
    const int gid = lane >> 2, tig = lane & 3;
    const int n0 = blockIdx.x * 128, m0 = blockIdx.y * 128;
    const int mz = (mode == 1) ? blockIdx.z : 0;
    const uint16_t* Ah = Ab  + (size_t)mz * TOK_ * D_;
    const uint16_t* Al = Alb + (size_t)mz * TOK_ * D_;
    const uint16_t* Bh = Bb  + (size_t)mz * 512 * 512;
    const uint16_t* Bl = Blb + (size_t)mz * 512 * 512;
    const float* bias = (mz == 0) ? b0p : (mz == 1) ? b1p : b2p;
    const int wm = w >> 2, wn = w & 3;
    const uint32_t sbase = (uint32_t)__cvta_generic_to_shared(sm);
    const int srow = tid >> 1;
    const uint32_t soff = (uint32_t)(srow * 80 + (tid & 1) * 32);
    const size_t goff = (size_t)srow * 512 + (tid & 1) * 16;

    float acc[4][4][4];
    #pragma unroll
    for (int i = 0; i < 4; i++)
        #pragma unroll
        for (int j = 0; j < 4; j++)
            #pragma unroll
            for (int kq = 0; kq < 4; kq++) acc[i][j][kq] = 0.f;

    {
        uint32_t b = sbase;
        cpa16(b + soff,          Ah + (size_t)m0 * 512 + goff);
        cpa16(b + soff + 16,     Ah + (size_t)m0 * 512 + goff + 8);
        cpa16(b + 10240 + soff,      Al + (size_t)m0 * 512 + goff);
        cpa16(b + 10240 + soff + 16, Al + (size_t)m0 * 512 + goff + 8);
        cpa16(b + 20480 + soff,      Bh + (size_t)n0 * 512 + goff);
        cpa16(b + 20480 + soff + 16, Bh + (size_t)n0 * 512 + goff + 8);
        cpa16(b + 30720 + soff,      Bl + (size_t)n0 * 512 + goff);
        cpa16(b + 30720 + soff + 16, Bl + (size_t)n0 * 512 + goff + 8);
        CP_COMMIT();
    }
    for (int c = 0; c < 16; c++) {
        if (c + 1 < 16) {
            uint32_t b = sbase + ((c + 1) & 1) * 40960;
            size_t g = goff + (c + 1) * 32;
            cpa16(b + soff,          Ah + (size_t)m0 * 512 + g);
            cpa16(b + soff + 16,     Ah + (size_t)m0 * 512 + g + 8);
            cpa16(b + 10240 + soff,      Al + (size_t)m0 * 512 + g);
            cpa16(b + 10240 + soff + 16, Al + (size_t)m0 * 512 + g + 8);
            cpa16(b + 20480 + soff,      Bh + (size_t)n0 * 512 + g);
            cpa16(b + 20480 + soff + 16, Bh + (size_t)n0 * 512 + g + 8);
            cpa16(b + 30720 + soff,      Bl + (size_t)n0 * 512 + g);
            cpa16(b + 30720 + soff + 16, Bl + (size_t)n0 * 512 + g + 8);
            CP_COMMIT();
            CP_WAIT1();
        } else {
            CP_WAIT0();
        }
        __syncthreads();
        const uint16_t* sAh = sm + (size_t)(c & 1) * 20480;
        const uint16_t* sAl = sAh + 5120;
        const uint16_t* sBh = sAh + 10240;
        const uint16_t* sBl = sAh + 15360;
        #pragma unroll
        for (int ks = 0; ks < 2; ks++) {
            const int dk = ks * 16 + 2 * tig;
            uint32_t ah[4][4], al[4][4], bhf[4][2], blf[4][2];
            #pragma unroll
            for (int mt = 0; mt < 4; mt++) {
                int ar = wm * 64 + mt * 16 + gid;
                ah[mt][0] = *(const uint32_t*)(sAh + ar * 40 + dk);
                ah[mt][1] = *(const uint32_t*)(sAh + (ar + 8) * 40 + dk);
                ah[mt][2] = *(const uint32_t*)(sAh + ar * 40 + dk + 8);
                ah[mt][3] = *(const uint32_t*)(sAh + (ar + 8) * 40 + dk + 8);
                al[mt][0] = *(const uint32_t*)(sAl + ar * 40 + dk);
                al[mt][1] = *(const uint32_t*)(sAl + (ar + 8) * 40 + dk);
                al[mt][2] = *(const uint32_t*)(sAl + ar * 40 + dk + 8);
                al[mt][3] = *(const uint32_t*)(sAl + (ar + 8) * 40 + dk + 8);
            }
            #pragma unroll
            for (int nt = 0; nt < 4; nt++) {
                int br = wn * 32 + nt * 8 + gid;
                bhf[nt][0] = *(const uint32_t*)(sBh + br * 40 + dk);
                bhf[nt][1] = *(const uint32_t*)(sBh + br * 40 + dk + 8);
                blf[nt][0] = *(const uint32_t*)(sBl + br * 40 + dk);
                blf[nt][1] = *(const uint32_t*)(sBl + br * 40 + dk + 8);
            }
            #pragma unroll
            for (int mt = 0; mt < 4; mt++)
                #pragma unroll
                for (int nt = 0; nt < 4; nt++) {
                    hmma(acc[mt][nt], ah[mt], bhf[nt][0], bhf[nt][1]);
                    hmma(acc[mt][nt], al[mt], bhf[nt][0], bhf[nt][1]);
                    hmma(acc[mt][nt], ah[mt], blf[nt][0], blf[nt][1]);
                }
        }
        __syncthreads();
    }
    #pragma unroll
    for (int mt = 0; mt < 4; mt++) {
        int row0 = m0 + wm * 64 + mt * 16 + gid, row1 = row0 + 8;
        #pragma unroll
        for (int nt = 0; nt < 4; nt++) {
            int nc = n0 + wn * 32 + nt * 8 + 2 * tig;
            float b0 = bias[nc], b1 = bias[nc + 1];
            float c00 = acc[mt][nt][0] + b0, c01 = acc[mt][nt][1] + b1;
            float c10 = acc[mt][nt][2] + b0, c11 = acc[mt][nt][3] + b1;
            if (mode == 0) {
                *(float2*)(Df + (size_t)row0 * 512 + nc) = make_float2(c00, c01);
                *(float2*)(Df + (size_t)row1 * 512 + nc) = make_float2(c10, c11);
            } else {
                int h = nc >> 6, dd = nc & 63;
                uint32_t hh, ll;
                int bb = row0 >> 11, tk = row0 & 2047;
                size_t o = ((size_t)mz * PO_) + (((size_t)(bb * H_ + h)) * S_ + tk) * DK_ + dd;
                splitpack(c00, c01, hh, ll);
                *(uint32_t*)(Dh + o) = hh; *(uint32_t*)(Dl + o) = ll;
                bb = row1 >> 11; tk = row1 & 2047;
                o = ((size_t)mz * PO_) + (((size_t)(bb * H_ + h)) * S_ + tk) * DK_ + dd;
                splitpack(c10, c11, hh, ll);
                *(uint32_t*)(Dh + o) = hh; *(uint32_t*)(Dl + o) = ll;
            }
        }
    }
}

// ---------------- K4: fused attention (R11 structure) ----------------
__global__ __launch_bounds__(256, 2)
void attn_mma(const uint16_t* __restrict__ ph, const uint16_t* __restrict__ pl,
              const float* __restrict__ pos, float* __restrict__ attn,
              float* __restrict__ rinv,
              uint16_t* __restrict__ xh, uint16_t* __restrict__ xl) {
    extern __shared__ uint16_t sm[];
    uint16_t* QH  = sm;
    uint16_t* QL  = sm + 9216;
    const int tid = threadIdx.x, w = tid >> 5, lane = tid & 31;
    const int gid = lane >> 2, tig = lane & 3;
    const int qt = blockIdx.x, bh = blockIdx.y, q0 = qt * 128;
    const uint16_t* qg  = ph;
    const uint16_t* qgl = pl;
    const uint16_t* kg  = ph + PO_;
    const uint16_t* kgl = pl + PO_;
    const uint16_t* vg  = ph + 2 * PO_;
    const uint16_t* vgl = pl + 2 * PO_;

    const uint32_t sbase = (uint32_t)__cvta_generic_to_shared(sm);
    const uint32_t loK = (lane & 7) * 144 + (lane >> 3) * 16;
    const uint32_t loV = (lane & 15) * 144 + (lane >> 4) * 16;
    const int vrow = tid >> 2;
    const uint32_t voff = (uint32_t)(vrow * 144 + (tid & 3) * 32);
    const size_t vgoff = (size_t)(tid & 3) * 16;

    {
        int row = tid >> 1, half = (tid & 1) * 32;
        const uint4* s1 = (const uint4*)(qg  + ((size_t)bh * S_ + q0 + row) * DK_ + half);
        const uint4* s2 = (const uint4*)(qgl + ((size_t)bh * S_ + q0 + row) * DK_ + half);
        uint4* d1 = (uint4*)(QH + row * 72 + half);
        uint4* d2 = (uint4*)(QL + row * 72 + half);
        #pragma unroll
        for (int j = 0; j < 4; j++) { d1[j] = s1[j]; d2[j] = s2[j]; }
    }
    __syncthreads();
    uint32_t qfh[4][4], qfl[4][4];
    {
        int qr = w * 16 + gid;
        #pragma unroll
        for (int ks = 0; ks < 4; ks++) {
            int dc = ks * 16 + 2 * tig;
            qfh[ks][0] = *(const uint32_t*)(QH + qr * 72 + dc);
            qfh[ks][1] = *(const uint32_t*)(QH + (qr + 8) * 72 + dc);
            qfh[ks][2] = *(const uint32_t*)(QH + qr * 72 + dc + 8);
            qfh[ks][3] = *(const uint32_t*)(QH + (qr + 8) * 72 + dc + 8);
            qfl[ks][0] = *(const uint32_t*)(QL + qr * 72 + dc);
            qfl[ks][1] = *(const uint32_t*)(QL + (qr + 8) * 72 + dc);
            qfl[ks][2] = *(const uint32_t*)(QL + qr * 72 + dc + 8);
            qfl[ks][3] = *(const uint32_t*)(QL + (qr + 8) * 72 + dc + 8);
        }
    }
    __syncthreads();

    const int r0 = q0 + w * 16 + gid, r1 = r0 + 8;
    float sum0 = 0.f, sum1 = 0.f;
    float accv[8][4];
    #pragma unroll
    for (int i = 0; i < 8; i++)
        #pragma unroll
        for (int j = 0; j < 4; j++) accv[i][j] = 0.f;
    uint32_t a01h[4], a01l[4];

    {
        size_t g = ((size_t)bh * S_ + vrow) * DK_ + vgoff;
        uint32_t b = sbase;
        cpa16(b + voff,              kg + g);
        cpa16(b + voff + 16,         kg + g + 8);
        cpa16(b + 9216 + voff,       kgl + g);
        cpa16(b + 9216 + voff + 16,  kgl + g + 8);
        cpa16(b + 18432 + voff,      vg + g);
        cpa16(b + 18432 + voff + 16, vg + g + 8);
        cpa16(b + 27648 + voff,      vgl + g);
        cpa16(b + 27648 + voff + 16, vgl + g + 8);
        CP_COMMIT();
    }
    for (int kt = 0; kt < 32; kt++) {
        const int k0 = kt * 64;
        if (kt + 1 < 32) {
            size_t g = ((size_t)bh * S_ + (kt + 1) * 64 + vrow) * DK_ + vgoff;
            uint32_t b = sbase + ((kt + 1) & 1) * 36864;
            cpa16(b + voff,              kg + g);
            cpa16(b + voff + 16,         kg + g + 8);
            cpa16(b + 9216 + voff,       kgl + g);
            cpa16(b + 9216 + voff + 16,  kgl + g + 8);
            cpa16(b + 18432 + voff,      vg + g);
            cpa16(b + 18432 + voff + 16, vg + g + 8);
            cpa16(b + 27648 + voff,      vgl + g);
            cpa16(b + 27648 + voff + 16, vgl + g + 8);
            CP_COMMIT();
            CP_WAIT1();
        } else {
            CP_WAIT0();
        }
        __syncthreads();
        const uint32_t bb0 = sbase + (kt & 1) * 36864;
        const uint32_t khb = bb0, klb = bb0 + 9216;
        const uint32_t vshb = bb0 + 18432, vslb = bb0 + 27648;

        #pragma unroll
        for (int nt = 0; nt < 8; nt++) {
            float s[4] = {0.f, 0.f, 0.f, 0.f};
            uint32_t kb[8], klo[8];
            ldsm4(kb[0], kb[1], kb[2], kb[3], khb + nt * 1152 + loK);
            ldsm4(kb[4], kb[5], kb[6], kb[7], khb + nt * 1152 + 64 + loK);
            ldsm4(klo[0], klo[1], klo[2], klo[3], klb + nt * 1152 + loK);
            ldsm4(klo[4], klo[5], klo[6], klo[7], klb + nt * 1152 + 64 + loK);
            #pragma unroll
            for (int ks = 0; ks < 4; ks++) {
                hmma(s, qfh[ks], kb[2 * ks], kb[2 * ks + 1]);
                hmma(s, qfl[ks], kb[2 * ks], kb[2 * ks + 1]);
                hmma(s, qfh[ks], klo[2 * ks], klo[2 * ks + 1]);
            }
            int col = k0 + nt * 8 + 2 * tig;
            float2 p0 = *(const float2*)(pos + (size_t)r0 * S_ + col);
            float2 p1 = *(const float2*)(pos + (size_t)r1 * S_ + col);
            float e0 = fexp(fmaf(s[0], 0.125f, p0.x));
            float e1 = fexp(fmaf(s[1], 0.125f, p0.y));
            float e2 = fexp(fmaf(s[2], 0.125f, p1.x));
            float e3 = fexp(fmaf(s[3], 0.125f, p1.y));
            sum0 += e0 + e1; sum1 += e2 + e3;
            *(float2*)(attn + ((size_t)bh * S_ + r0) * S_ + col) = make_float2(e0, e1);
            *(float2*)(attn + ((size_t)bh * S_ + r1) * S_ + col) = make_float2(e2, e3);
            uint32_t h0, l0, h1, l1;
            splitpack(e0, e1, h0, l0);
            splitpack(e2, e3, h1, l1);
            if ((nt & 1) == 0) {
                a01h[0] = h0; a01h[1] = h1; a01l[0] = l0; a01l[1] = l1;
            } else {
                a01h[2] = h0; a01h[3] = h1; a01l[2] = l0; a01l[3] = l1;
                int kc = nt >> 1;
                #pragma unroll
                for (int dtp = 0; dtp < 4; dtp++) {
                    uint32_t vh4[4], vl4[4];
                    ldsm4t(vh4[0], vh4[1], vh4[2], vh4[3], vshb + kc * 2304 + dtp * 32 + loV);
                    ldsm4t(vl4[0], vl4[1], vl4[2], vl4[3], vslb + kc * 2304 + dtp * 32 + loV);
                    hmma(accv[2 * dtp],     a01h, vh4[0], vh4[1]);
                    hmma(accv[2 * dtp],     a01l, vh4[0], vh4[1]);
                    hmma(accv[2 * dtp],     a01h, vl4[0], vl4[1]);
                    hmma(accv[2 * dtp + 1], a01h, vh4[2], vh4[3]);
                    hmma(accv[2 * dtp + 1], a01l, vh4[2], vh4[3]);
                    hmma(accv[2 * dtp + 1], a01h, vl4[2], vl4[3]);
                }
            }
        }
        __syncthreads();
    }
    sum0 += __shfl_xor_sync(0xffffffffu, sum0, 1);
    sum0 += __shfl_xor_sync(0xffffffffu, sum0, 2);
    sum1 += __shfl_xor_sync(0xffffffffu, sum1, 1);
    sum1 += __shfl_xor_sync(0xffffffffu, sum1, 2);
    float inv0 = 1.f / sum0, inv1 = 1.f / sum1;
    if (tig == 0) { rinv[bh * S_ + r0] = inv0; rinv[bh * S_ + r1] = inv1; }
    const int bb = bh >> 3, h = bh & 7;
    #pragma unroll
    for (int dt = 0; dt < 8; dt++) {
        int col = dt * 8 + 2 * tig;
        uint32_t hh, ll;
        splitpack(accv[dt][0] * inv0, accv[dt][1] * inv0, hh, ll);
        *(uint32_t*)(xh + ((size_t)(bb * S_ + r0)) * D_ + h * DK_ + col) = hh;
        *(uint32_t*)(xl + ((size_t)(bb * S_ + r0)) * D_ + h * DK_ + col) = ll;
        splitpack(accv[dt][2] * inv1, accv[dt][3] * inv1, hh, ll);
        *(uint32_t*)(xh + ((size_t)(bb * S_ + r1)) * D_ + h * DK_ + col) = hh;
        *(uint32_t*)(xl + ((size_t)(bb * S_ + r1)) * D_ + h * DK_ + col) = ll;
    }
}

// ---------------- launch ----------------
extern "C" void kernel_launch(void* const* d_in, const int* in_sizes, int n_in,
                              void* d_out, int out_size) {
    const float* q     = (const float*)d_in[0];
    const float* k     = (const float*)d_in[1];
    const float* v     = (const float*)d_in[2];
    const float* pos_k = (const float*)d_in[4];
    const float* ln_w  = (const float*)d_in[5];
    const float* ln_b  = (const float*)d_in[6];
    const float* Wq    = (const float*)d_in[7];
    const float* bq    = (const float*)d_in[8];
    const float* Wk    = (const float*)d_in[9];
    const float* bk    = (const float*)d_in[10];
    const float* Wv    = (const float*)d_in[11];
    const float* bv    = (const float*)d_in[12];
    const float* Wo    = (const float*)d_in[13];
    const float* bo    = (const float*)d_in[14];
    float* out = (float*)d_out;

    uint16_t *xnh, *xnl, *wh, *wl, *phh, *phl, *xh, *xl;
    float *rinv, *attn;
    cudaGetSymbolAddress((void**)&xnh, g_xnh);
    cudaGetSymbolAddress((void**)&xnl, g_xnl);
    cudaGetSymbolAddress((void**)&wh, g_wh);
    cudaGetSymbolAddress((void**)&wl, g_wl);
    cudaGetSymbolAddress((void**)&phh, g_phh);
    cudaGetSymbolAddress((void**)&phl, g_phl);
    cudaGetSymbolAddress((void**)&xh, g_xh);
    cudaGetSymbolAddress((void**)&xl, g_xl);
    cudaGetSymbolAddress((void**)&rinv, g_rinv);
    if ((size_t)out_size >= OUT_ELEMS + ATTN_ELEMS) {
        attn = out + OUT_ELEMS;
    } else {
        cudaGetSymbolAddress((void**)&attn, g_attn_scratch);
    }

    cudaFuncSetAttribute(gemm_mma, cudaFuncAttributeMaxDynamicSharedMemorySize, 81920);
    cudaFuncSetAttribute(attn_mma, cudaFuncAttributeMaxDynamicSharedMemorySize, 73728);

    ln_split<<<dim3(TOK_, 3), 128>>>(q, k, v, ln_w, ln_b, xnh, xnl);
    wsplit<<<dim3(512, 4), 128>>>(Wq, Wk, Wv, Wo, wh, wl);

    const size_t WO = 512ull * 512ull;
    gemm_mma<<<dim3(4, 64, 3), 256, 81920>>>(xnh, xnl, wh, wl, bq, bk, bv,
                                             phh, phl, nullptr, 1, nullptr, nullptr);
    attn_mma<<<dim3(16, 32), 256, 73728>>>(phh, phl, pos_k, attn, rinv, xh, xl);
    // z=0: out-proj GEMM; z=1,2: attn rescale (512 blocks, MLP-8 batched)
    gemm_mma<<<dim3(4, 64, 3), 256, 81920>>>(xh, xl, wh + 3 * WO, wl + 3 * WO,
                                             bo, bo, bo, nullptr, nullptr, out, 0,
                                             attn, rinv);
}

// round 16
// speedup vs baseline: 1.0233x; 1.0019x over previous
#include <cuda_runtime.h>
#include <cuda_bf16.h>
#include <cstdint>

#define S_ 2048
#define D_ 512
#define H_ 8
#define DK_ 64
#define BH_ 32
#define TOK_ 8192
#define OUT_ELEMS 4194304ull
#define ATTN_ELEMS 134217728ull
#define PO_ 4194304ull

__device__ uint16_t g_xnh[3ull * TOK_ * D_];
__device__ uint16_t g_xnl[3ull * TOK_ * D_];
__device__ uint16_t g_wh[4ull * 512 * 512];
__device__ uint16_t g_wl[4ull * 512 * 512];
__device__ uint16_t g_phh[3ull * PO_];
__device__ uint16_t g_phl[3ull * PO_];
__device__ uint16_t g_xh[(size_t)TOK_ * D_];
__device__ uint16_t g_xl[(size_t)TOK_ * D_];
__device__ float g_rinv[BH_ * S_];
__device__ float g_attn_scratch[ATTN_ELEMS];

__device__ __forceinline__ void hmma(float c[4], const uint32_t a[4], uint32_t b0, uint32_t b1) {
    asm("mma.sync.aligned.m16n8k16.row.col.f32.bf16.bf16.f32 "
        "{%0,%1,%2,%3},{%4,%5,%6,%7},{%8,%9},{%0,%1,%2,%3};"
        : "+f"(c[0]), "+f"(c[1]), "+f"(c[2]), "+f"(c[3])
        : "r"(a[0]), "r"(a[1]), "r"(a[2]), "r"(a[3]), "r"(b0), "r"(b1));
}
__device__ __forceinline__ void ldsm4(uint32_t& r0, uint32_t& r1, uint32_t& r2, uint32_t& r3,
                                      uint32_t addr) {
    asm volatile("ldmatrix.sync.aligned.m8n8.x4.shared.b16 {%0,%1,%2,%3}, [%4];"
                 : "=r"(r0), "=r"(r1), "=r"(r2), "=r"(r3) : "r"(addr));
}
__device__ __forceinline__ void ldsm4t(uint32_t& r0, uint32_t& r1, uint32_t& r2, uint32_t& r3,
                                       uint32_t addr) {
    asm volatile("ldmatrix.sync.aligned.m8n8.x4.trans.shared.b16 {%0,%1,%2,%3}, [%4];"
                 : "=r"(r0), "=r"(r1), "=r"(r2), "=r"(r3) : "r"(addr));
}
__device__ __forceinline__ void cpa16(uint32_t dst, const void* src) {
    asm volatile("cp.async.cg.shared.global [%0], [%1], 16;" :: "r"(dst), "l"(src));
}
#define CP_COMMIT() asm volatile("cp.async.commit_group;")
#define CP_WAIT0()  asm volatile("cp.async.wait_group 0;")
#define CP_WAIT1()  asm volatile("cp.async.wait_group 1;")
__device__ __forceinline__ void splitpack(float f0, float f1, uint32_t& h, uint32_t& l) {
    asm("cvt.rn.bf16x2.f32 %0, %1, %2;" : "=r"(h) : "f"(f1), "f"(f0));
    float g0 = __uint_as_float(h << 16);
    float g1 = __uint_as_float(h & 0xffff0000u);
    asm("cvt.rn.bf16x2.f32 %0, %1, %2;" : "=r"(l) : "f"(f1 - g1), "f"(f0 - g0));
}
__device__ __forceinline__ float fexp(float x) {
    float t = x * 1.4426950408889634f;
    t = fmaxf(t, -126.0f);
    float z = t + 12582912.0f;
    int   n = (__float_as_int(z) & 0x7FFFFF) - 0x400000;
    float f = t - (z - 12582912.0f);
    float p = 1.5403530e-4f;
    p = fmaf(p, f, 1.3333558e-3f);
    p = fmaf(p, f, 9.6181291e-3f);
    p = fmaf(p, f, 5.5504109e-2f);
    p = fmaf(p, f, 2.4022651e-1f);
    p = fmaf(p, f, 6.9314718e-1f);
    p = fmaf(p, f, 1.0f);
    return __int_as_float(__float_as_int(p) + (n << 23));
}

// ---------------- K1: LayerNorm -> split bf16 ----------------
__global__ void ln_split(const float* __restrict__ q, const float* __restrict__ k,
                         const float* __restrict__ v, const float* __restrict__ w,
                         const float* __restrict__ b,
                         uint16_t* __restrict__ xh, uint16_t* __restrict__ xl) {
    const int row = blockIdx.x, which = blockIdx.y, tid = threadIdx.x;
    const float* src = (which == 0) ? q : (which == 1) ? k : v;
    float4 x = *(const float4*)(src + (size_t)row * D_ + tid * 4);
    float s  = x.x + x.y + x.z + x.w;
    float ss = x.x * x.x + x.y * x.y + x.z * x.z + x.w * x.w;
    __shared__ float red[2][4];
    #pragma unroll
    for (int o = 16; o; o >>= 1) {
        s  += __shfl_xor_sync(0xffffffffu, s, o);
        ss += __shfl_xor_sync(0xffffffffu, ss, o);
    }
    if ((tid & 31) == 0) { red[0][tid >> 5] = s; red[1][tid >> 5] = ss; }
    __syncthreads();
    s  = red[0][0] + red[0][1] + red[0][2] + red[0][3];
    ss = red[1][0] + red[1][1] + red[1][2] + red[1][3];
    const float mu  = s * (1.0f / D_);
    const float var = ss * (1.0f / D_) - mu * mu;
    const float r   = rsqrtf(var + 1e-5f);
    float4 wv = *(const float4*)(w + tid * 4);
    float4 bv = *(const float4*)(b + tid * 4);
    float o0 = (x.x - mu) * r * wv.x + bv.x;
    float o1 = (x.y - mu) * r * wv.y + bv.y;
    float o2 = (x.z - mu) * r * wv.z + bv.z;
    float o3 = (x.w - mu) * r * wv.w + bv.w;
    uint32_t h01, l01, h23, l23;
    splitpack(o0, o1, h01, l01); splitpack(o2, o3, h23, l23);
    size_t base = ((size_t)which * TOK_ + row) * D_ + tid * 4;
    *(uint32_t*)(xh + base) = h01; *(uint32_t*)(xh + base + 2) = h23;
    *(uint32_t*)(xl + base) = l01; *(uint32_t*)(xl + base + 2) = l23;
}

// ---------------- K2: split weights ----------------
__global__ void wsplit(const float* __restrict__ Wq, const float* __restrict__ Wk,
                       const float* __restrict__ Wv, const float* __restrict__ Wo,
                       uint16_t* __restrict__ wh, uint16_t* __restrict__ wl) {
    const int row = blockIdx.x, mat = blockIdx.y, tid = threadIdx.x;
    const float* W = (mat == 0) ? Wq : (mat == 1) ? Wk : (mat == 2) ? Wv : Wo;
    float4 x = *(const float4*)(W + (size_t)row * 512 + tid * 4);
    uint32_t h01, l01, h23, l23;
    splitpack(x.x, x.y, h01, l01); splitpack(x.z, x.w, h23, l23);
    size_t base = ((size_t)mat * 512 + row) * 512 + tid * 4;
    *(uint32_t*)(wh + base) = h01; *(uint32_t*)(wh + base + 2) = h23;
    *(uint32_t*)(wl + base) = l01; *(uint32_t*)(wl + base + 2) = l23;
}

// ---------------- K3: batched projections / K5: out-proj + parallel rescale ----------------
__global__ __launch_bounds__(256, 2)
void gemm_mma(const uint16_t* __restrict__ Ab, const uint16_t* __restrict__ Alb,
              const uint16_t* __restrict__ Bb, const uint16_t* __restrict__ Blb,
              const float* __restrict__ b0p, const float* __restrict__ b1p,
              const float* __restrict__ b2p,
              uint16_t* __restrict__ Dh, uint16_t* __restrict__ Dl,
              float* __restrict__ Df, int mode,
              float* __restrict__ attn, const float* __restrict__ rinvp) {
    extern __shared__ uint16_t sm[];
    const int tid = threadIdx.x;
    if (mode == 0 && blockIdx.z >= 1) {
        int rid = (blockIdx.z - 1) * 256 + blockIdx.y * 4 + blockIdx.x;
        int bh = rid >> 4, r0 = (rid & 15) * 128;
        for (int rg = 0; rg < 32; rg++) {
            int br = r0 + rg * 4;
            float inv0 = rinvp[bh * S_ + br];
            float inv1 = rinvp[bh * S_ + br + 1];
            float inv2 = rinvp[bh * S_ + br + 2];
            float inv3 = rinvp[bh * S_ + br + 3];
            float4* p0 = (float4*)(attn + ((size_t)bh * S_ + br) * S_);
            float4* p1 = (float4*)(attn + ((size_t)bh * S_ + br + 1) * S_);
            float4* p2 = (float4*)(attn + ((size_t)bh * S_ + br + 2) * S_);
            float4* p3 = (float4*)(attn + ((size_t)bh * S_ + br + 3) * S_);
            float4 a0 = p0[tid], b0 = p0[tid + 256];
            float4 a1 = p1[tid], b1 = p1[tid + 256];
            float4 a2 = p2[tid], b2 = p2[tid + 256];
            float4 a3 = p3[tid], b3 = p3[tid + 256];
            a0.x *= inv0; a0.y *= inv0; a0.z *= inv0; a0.w *= inv0;
            b0.x *= inv0; b0.y *= inv0; b0.z *= inv0; b0.w *= inv0;
            a1.x *= inv1; a1.y *= inv1; a1.z *= inv1; a1.w *= inv1;
            b1.x *= inv1; b1.y *= inv1; b1.z *= inv1; b1.w *= inv1;
            a2.x *= inv2; a2.y *= inv2; a2.z *= inv2; a2.w *= inv2;
            b2.x *= inv2; b2.y *= inv2; b2.z *= inv2; b2.w *= inv2;
            a3.x *= inv3; a3.y *= inv3; a3.z *= inv3; a3.w *= inv3;
            b3.x *= inv3; b3.y *= inv3; b3.z *= inv3; b3.w *= inv3;
            p0[tid] = a0; p0[tid + 256] = b0;
            p1[tid] = a1; p1[tid + 256] = b1;
            p2[tid] = a2; p2[tid + 256] = b2;
            p3[tid] = a3; p3[tid + 256] = b3;
        }
        return;
    }
    const int w = tid >> 5, lane = tid & 31;
    const int gid = lane >> 2, tig = lane & 3;
    const int n0 = blockIdx.x * 128, m0 = blockIdx.y * 128;
    const int mz = (mode == 1) ? blockIdx.z : 0;
    const uint16_t* Ah = Ab  + (size_t)mz * TOK_ * D_;
    const uint16_t* Al = Alb + (size_t)mz * TOK_ * D_;
    const uint16_t* Bh = Bb  + (size_t)mz * 512 * 512;
    const uint16_t* Bl = Blb + (size_t)mz * 512 * 512;
    const float* bias = (mz == 0) ? b0p : (mz == 1) ? b1p : b2p;
    const int wm = w >> 2, wn = w & 3;
    const uint32_t sbase = (uint32_t)__cvta_generic_to_shared(sm);
    const int srow = tid >> 1;
    const uint32_t soff = (uint32_t)(srow * 80 + (tid & 1) * 32);
    const size_t goff = (size_t)srow * 512 + (tid & 1) * 16;
    // ldmatrix per-lane offsets (80B rows)
    const uint32_t loA = (lane & 15) * 80 + (lane >> 4) * 16;
    const uint32_t loB = (lane & 7) * 80 + (lane >> 3) * 16;

    float acc[4][4][4];
    #pragma unroll
    for (int i = 0; i < 4; i++)
        #pragma unroll
        for (int j = 0; j < 4; j++)
            #pragma unroll
            for (int kq = 0; kq < 4; kq++) acc[i][j][kq] = 0.f;

    {
        uint32_t b = sbase;
        cpa16(b + soff,          Ah + (size_t)m0 * 512 + goff);
        cpa16(b + soff + 16,     Ah + (size_t)m0 * 512 + goff + 8);
        cpa16(b + 10240 + soff,      Al + (size_t)m0 * 512 + goff);
        cpa16(b + 10240 + soff + 16, Al + (size_t)m0 * 512 + goff + 8);
        cpa16(b + 20480 + soff,      Bh + (size_t)n0 * 512 + goff);
        cpa16(b + 20480 + soff + 16, Bh + (size_t)n0 * 512 + goff + 8);
        cpa16(b + 30720 + soff,      Bl + (size_t)n0 * 512 + goff);
        cpa16(b + 30720 + soff + 16, Bl + (size_t)n0 * 512 + goff + 8);
        CP_COMMIT();
    }
    for (int c = 0; c < 16; c++) {
        if (c + 1 < 16) {
            uint32_t b = sbase + ((c + 1) & 1) * 40960;
            size_t g = goff + (c + 1) * 32;
            cpa16(b + soff,          Ah + (size_t)m0 * 512 + g);
            cpa16(b + soff + 16,     Ah + (size_t)m0 * 512 + g + 8);
            cpa16(b + 10240 + soff,      Al + (size_t)m0 * 512 + g);
            cpa16(b + 10240 + soff + 16, Al + (size_t)m0 * 512 + g + 8);
            cpa16(b + 20480 + soff,      Bh + (size_t)n0 * 512 + g);
            cpa16(b + 20480 + soff + 16, Bh + (size_t)n0 * 512 + g + 8);
            cpa16(b + 30720 + soff,      Bl + (size_t)n0 * 512 + g);
            cpa16(b + 30720 + soff + 16, Bl + (size_t)n0 * 512 + g + 8);
            CP_COMMIT();
            CP_WAIT1();
        } else {
            CP_WAIT0();
        }
        __syncthreads();
        const uint32_t aB  = sbase + (c & 1) * 40960;
        const uint32_t alB = aB + 10240;
        const uint32_t bB  = aB + 20480;
        const uint32_t blB = aB + 30720;

        // B fragments: one ldsm4 per nt covers both ks halves (hi and lo)
        uint32_t bhf[4][4], blf[4][4];
        #pragma unroll
        for (int nt = 0; nt < 4; nt++) {
            uint32_t br = (uint32_t)(wn * 32 + nt * 8) * 80;
            ldsm4(bhf[nt][0], bhf[nt][1], bhf[nt][2], bhf[nt][3], bB + br + loB);
            ldsm4(blf[nt][0], blf[nt][1], blf[nt][2], blf[nt][3], blB + br + loB);
        }
        #pragma unroll
        for (int ks = 0; ks < 2; ks++) {
            uint32_t ah[4][4], al[4][4];
            #pragma unroll
            for (int mt = 0; mt < 4; mt++) {
                uint32_t ab = (uint32_t)((wm * 64 + mt * 16) * 80 + ks * 32);
                ldsm4(ah[mt][0], ah[mt][1], ah[mt][2], ah[mt][3], aB + ab + loA);
                ldsm4(al[mt][0], al[mt][1], al[mt][2], al[mt][3], alB + ab + loA);
            }
            #pragma unroll
            for (int mt = 0; mt < 4; mt++)
                #pragma unroll
                for (int nt = 0; nt < 4; nt++) {
                    hmma(acc[mt][nt], ah[mt], bhf[nt][2 * ks], bhf[nt][2 * ks + 1]);
                    hmma(acc[mt][nt], al[mt], bhf[nt][2 * ks], bhf[nt][2 * ks + 1]);
                    hmma(acc[mt][nt], ah[mt], blf[nt][2 * ks], blf[nt][2 * ks + 1]);
                }
        }
        __syncthreads();
    }
    #pragma unroll
    for (int mt = 0; mt < 4; mt++) {
        int row0 = m0 + wm * 64 + mt * 16 + gid, row1 = row0 + 8;
        #pragma unroll
        for (int nt = 0; nt < 4; nt++) {
            int nc = n0 + wn * 32 + nt * 8 + 2 * tig;
            float b0 = bias[nc], b1 = bias[nc + 1];
            float c00 = acc[mt][nt][0] + b0, c01 = acc[mt][nt][1] + b1;
            float c10 = acc[mt][nt][2] + b0, c11 = acc[mt][nt][3] + b1;
            if (mode == 0) {
                *(float2*)(Df + (size_t)row0 * 512 + nc) = make_float2(c00, c01);
                *(float2*)(Df + (size_t)row1 * 512 + nc) = make_float2(c10, c11);
            } else {
                int h = nc >> 6, dd = nc & 63;
                uint32_t hh, ll;
                int bb = row0 >> 11, tk = row0 & 2047;
                size_t o = ((size_t)mz * PO_) + (((size_t)(bb * H_ + h)) * S_ + tk) * DK_ + dd;
                splitpack(c00, c01, hh, ll);
                *(uint32_t*)(Dh + o) = hh; *(uint32_t*)(Dl + o) = ll;
                bb = row1 >> 11; tk = row1 & 2047;
                o = ((size_t)mz * PO_) + (((size_t)(bb * H_ + h)) * S_ + tk) * DK_ + dd;
                splitpack(c10, c11, hh, ll);
                *(uint32_t*)(Dh + o) = hh; *(uint32_t*)(Dl + o) = ll;
            }
        }
    }
}

// ---------------- K4: fused attention (R11 structure) ----------------
__global__ __launch_bounds__(256, 2)
void attn_mma(const uint16_t* __restrict__ ph, const uint16_t* __restrict__ pl,
              const float* __restrict__ pos, float* __restrict__ attn,
              float* __restrict__ rinv,
              uint16_t* __restrict__ xh, uint16_t* __restrict__ xl) {
    extern __shared__ uint16_t sm[];
    uint16_t* QH  = sm;
    uint16_t* QL  = sm + 9216;
    const int tid = threadIdx.x, w = tid >> 5, lane = tid & 31;
    const int gid = lane >> 2, tig = lane & 3;
    const int qt = blockIdx.x, bh = blockIdx.y, q0 = qt * 128;
    const uint16_t* qg  = ph;
    const uint16_t* qgl = pl;
    const uint16_t* kg  = ph + PO_;
    const uint16_t* kgl = pl + PO_;
    const uint16_t* vg  = ph + 2 * PO_;
    const uint16_t* vgl = pl + 2 * PO_;

    const uint32_t sbase = (uint32_t)__cvta_generic_to_shared(sm);
    const uint32_t loK = (lane & 7) * 144 + (lane >> 3) * 16;
    const uint32_t loV = (lane & 15) * 144 + (lane >> 4) * 16;
    const int vrow = tid >> 2;
    const uint32_t voff = (uint32_t)(vrow * 144 + (tid & 3) * 32);
    const size_t vgoff = (size_t)(tid & 3) * 16;

    {
        int row = tid >> 1, half = (tid & 1) * 32;
        const uint4* s1 = (const uint4*)(qg  + ((size_t)bh * S_ + q0 + row) * DK_ + half);
        const uint4* s2 = (const uint4*)(qgl + ((size_t)bh * S_ + q0 + row) * DK_ + half);
        uint4* d1 = (uint4*)(QH + row * 72 + half);
        uint4* d2 = (uint4*)(QL + row * 72 + half);
        #pragma unroll
        for (int j = 0; j < 4; j++) { d1[j] = s1[j]; d2[j] = s2[j]; }
    }
    __syncthreads();
    uint32_t qfh[4][4], qfl[4][4];
    {
        int qr = w * 16 + gid;
        #pragma unroll
        for (int ks = 0; ks < 4; ks++) {
            int dc = ks * 16 + 2 * tig;
            qfh[ks][0] = *(const uint32_t*)(QH + qr * 72 + dc);
            qfh[ks][1] = *(const uint32_t*)(QH + (qr + 8) * 72 + dc);
            qfh[ks][2] = *(const uint32_t*)(QH + qr * 72 + dc + 8);
            qfh[ks][3] = *(const uint32_t*)(QH + (qr + 8) * 72 + dc + 8);
            qfl[ks][0] = *(const uint32_t*)(QL + qr * 72 + dc);
            qfl[ks][1] = *(const uint32_t*)(QL + (qr + 8) * 72 + dc);
            qfl[ks][2] = *(const uint32_t*)(QL + qr * 72 + dc + 8);
            qfl[ks][3] = *(const uint32_t*)(QL + (qr + 8) * 72 + dc + 8);
        }
    }
    __syncthreads();

    const int r0 = q0 + w * 16 + gid, r1 = r0 + 8;
    float sum0 = 0.f, sum1 = 0.f;
    float accv[8][4];
    #pragma unroll
    for (int i = 0; i < 8; i++)
        #pragma unroll
        for (int j = 0; j < 4; j++) accv[i][j] = 0.f;
    uint32_t a01h[4], a01l[4];

    {
        size_t g = ((size_t)bh * S_ + vrow) * DK_ + vgoff;
        uint32_t b = sbase;
        cpa16(b + voff,              kg + g);
        cpa16(b + voff + 16,         kg + g + 8);
        cpa16(b + 9216 + voff,       kgl + g);
        cpa16(b + 9216 + voff + 16,  kgl + g + 8);
        cpa16(b + 18432 + voff,      vg + g);
        cpa16(b + 18432 + voff + 16, vg + g + 8);
        cpa16(b + 27648 + voff,      vgl + g);
        cpa16(b + 27648 + voff + 16, vgl + g + 8);
        CP_COMMIT();
    }
    for (int kt = 0; kt < 32; kt++) {
        const int k0 = kt * 64;
        if (kt + 1 < 32) {
            size_t g = ((size_t)bh * S_ + (kt + 1) * 64 + vrow) * DK_ + vgoff;
            uint32_t b = sbase + ((kt + 1) & 1) * 36864;
            cpa16(b + voff,              kg + g);
            cpa16(b + voff + 16,         kg + g + 8);
            cpa16(b + 9216 + voff,       kgl + g);
            cpa16(b + 9216 + voff + 16,  kgl + g + 8);
            cpa16(b + 18432 + voff,      vg + g);
            cpa16(b + 18432 + voff + 16, vg + g + 8);
            cpa16(b + 27648 + voff,      vgl + g);
            cpa16(b + 27648 + voff + 16, vgl + g + 8);
            CP_COMMIT();
            CP_WAIT1();
        } else {
            CP_WAIT0();
        }
        __syncthreads();
        const uint32_t bb0 = sbase + (kt & 1) * 36864;
        const uint32_t khb = bb0, klb = bb0 + 9216;
        const uint32_t vshb = bb0 + 18432, vslb = bb0 + 27648;

        #pragma unroll
        for (int nt = 0; nt < 8; nt++) {
            float s[4] = {0.f, 0.f, 0.f, 0.f};
            uint32_t kb[8], klo[8];
            ldsm4(kb[0], kb[1], kb[2], kb[3], khb + nt * 1152 + loK);
            ldsm4(kb[4], kb[5], kb[6], kb[7], khb + nt * 1152 + 64 + loK);
            ldsm4(klo[0], klo[1], klo[2], klo[3], klb + nt * 1152 + loK);
            ldsm4(klo[4], klo[5], klo[6], klo[7], klb + nt * 1152 + 64 + loK);
            #pragma unroll
            for (int ks = 0; ks < 4; ks++) {
                hmma(s, qfh[ks], kb[2 * ks], kb[2 * ks + 1]);
                hmma(s, qfl[ks], kb[2 * ks], kb[2 * ks + 1]);
                hmma(s, qfh[ks], klo[2 * ks], klo[2 * ks + 1]);
            }
            int col = k0 + nt * 8 + 2 * tig;
            float2 p0 = *(const float2*)(pos + (size_t)r0 * S_ + col);
            float2 p1 = *(const float2*)(pos + (size_t)r1 * S_ + col);
            float e0 = fexp(fmaf(s[0], 0.125f, p0.x));
            float e1 = fexp(fmaf(s[1], 0.125f, p0.y));
            float e2 = fexp(fmaf(s[2], 0.125f, p1.x));
            float e3 = fexp(fmaf(s[3], 0.125f, p1.y));
            sum0 += e0 + e1; sum1 += e2 + e3;
            *(float2*)(attn + ((size_t)bh * S_ + r0) * S_ + col) = make_float2(e0, e1);
            *(float2*)(attn + ((size_t)bh * S_ + r1) * S_ + col) = make_float2(e2, e3);
            uint32_t h0, l0, h1, l1;
            splitpack(e0, e1, h0, l0);
            splitpack(e2, e3, h1, l1);
            if ((nt & 1) == 0) {
                a01h[0] = h0; a01h[1] = h1; a01l[0] = l0; a01l[1] = l1;
            } else {
                a01h[2] = h0; a01h[3] = h1; a01l[2] = l0; a01l[3] = l1;
                int kc = nt >> 1;
                #pragma unroll
                for (int dtp = 0; dtp < 4; dtp++) {
                    uint32_t vh4[4], vl4[4];
                    ldsm4t(vh4[0], vh4[1], vh4[2], vh4[3], vshb + kc * 2304 + dtp * 32 + loV);
                    ldsm4t(vl4[0], vl4[1], vl4[2], vl4[3], vslb + kc * 2304 + dtp * 32 + loV);
                    hmma(accv[2 * dtp],     a01h, vh4[0], vh4[1]);
                    hmma(accv[2 * dtp],     a01l, vh4[0], vh4[1]);
                    hmma(accv[2 * dtp],     a01h, vl4[0], vl4[1]);
                    hmma(accv[2 * dtp + 1], a01h, vh4[2], vh4[3]);
                    hmma(accv[2 * dtp + 1], a01l, vh4[2], vh4[3]);
                    hmma(accv[2 * dtp + 1], a01h, vl4[2], vl4[3]);
                }
            }
        }
        __syncthreads();
    }
    sum0 += __shfl_xor_sync(0xffffffffu, sum0, 1);
    sum0 += __shfl_xor_sync(0xffffffffu, sum0, 2);
    sum1 += __shfl_xor_sync(0xffffffffu, sum1, 1);
    sum1 += __shfl_xor_sync(0xffffffffu, sum1, 2);
    float inv0 = 1.f / sum0, inv1 = 1.f / sum1;
    if (tig == 0) { rinv[bh * S_ + r0] = inv0; rinv[bh * S_ + r1] = inv1; }
    const int bb = bh >> 3, h = bh & 7;
    #pragma unroll
    for (int dt = 0; dt < 8; dt++) {
        int col = dt * 8 + 2 * tig;
        uint32_t hh, ll;
        splitpack(accv[dt][0] * inv0, accv[dt][1] * inv0, hh, ll);
        *(uint32_t*)(xh + ((size_t)(bb * S_ + r0)) * D_ + h * DK_ + col) = hh;
        *(uint32_t*)(xl + ((size_t)(bb * S_ + r0)) * D_ + h * DK_ + col) = ll;
        splitpack(accv[dt][2] * inv1, accv[dt][3] * inv1, hh, ll);
        *(uint32_t*)(xh + ((size_t)(bb * S_ + r1)) * D_ + h * DK_ + col) = hh;
        *(uint32_t*)(xl + ((size_t)(bb * S_ + r1)) * D_ + h * DK_ + col) = ll;
    }
}

// ---------------- launch ----------------
extern "C" void kernel_launch(void* const* d_in, const int* in_sizes, int n_in,
                              void* d_out, int out_size) {
    const float* q     = (const float*)d_in[0];
    const float* k     = (const float*)d_in[1];
    const float* v     = (const float*)d_in[2];
    const float* pos_k = (const float*)d_in[4];
    const float* ln_w  = (const float*)d_in[5];
    const float* ln_b  = (const float*)d_in[6];
    const float* Wq    = (const float*)d_in[7];
    const float* bq    = (const float*)d_in[8];
    const float* Wk    = (const float*)d_in[9];
    const float* bk    = (const float*)d_in[10];
    const float* Wv    = (const float*)d_in[11];
    const float* bv    = (const float*)d_in[12];
    const float* Wo    = (const float*)d_in[13];
    const float* bo    = (const float*)d_in[14];
    float* out = (float*)d_out;

    uint16_t *xnh, *xnl, *wh, *wl, *phh, *phl, *xh, *xl;
    float *rinv, *attn;
    cudaGetSymbolAddress((void**)&xnh, g_xnh);
    cudaGetSymbolAddress((void**)&xnl, g_xnl);
    cudaGetSymbolAddress((void**)&wh, g_wh);
    cudaGetSymbolAddress((void**)&wl, g_wl);
    cudaGetSymbolAddress((void**)&phh, g_phh);
    cudaGetSymbolAddress((void**)&phl, g_phl);
    cudaGetSymbolAddress((void**)&xh, g_xh);
    cudaGetSymbolAddress((void**)&xl, g_xl);
    cudaGetSymbolAddress((void**)&rinv, g_rinv);
    if ((size_t)out_size >= OUT_ELEMS + ATTN_ELEMS) {
        attn = out + OUT_ELEMS;
    } else {
        cudaGetSymbolAddress((void**)&attn, g_attn_scratch);
    }

    cudaFuncSetAttribute(gemm_mma, cudaFuncAttributeMaxDynamicSharedMemorySize, 81920);
    cudaFuncSetAttribute(attn_mma, cudaFuncAttributeMaxDynamicSharedMemorySize, 73728);

    ln_split<<<dim3(TOK_, 3), 128>>>(q, k, v, ln_w, ln_b, xnh, xnl);
    wsplit<<<dim3(512, 4), 128>>>(Wq, Wk, Wv, Wo, wh, wl);

    const size_t WO = 512ull * 512ull;
    gemm_mma<<<dim3(4, 64, 3), 256, 81920>>>(xnh, xnl, wh, wl, bq, bk, bv,
                                             phh, phl, nullptr, 1, nullptr, nullptr);
    attn_mma<<<dim3(16, 32), 256, 73728>>>(phh, phl, pos_k, attn, rinv, xh, xl);
    gemm_mma<<<dim3(4, 64, 3), 256, 81920>>>(xh, xl, wh + 3 * WO, wl + 3 * WO,
                                             bo, bo, bo, nullptr, nullptr, out, 0,
                                             attn, rinv);
}

// round 17
// speedup vs baseline: 1.0428x; 1.0191x over previous
#include <cuda_runtime.h>
#include <cuda_bf16.h>
#include <cstdint>

#define S_ 2048
#define D_ 512
#define H_ 8
#define DK_ 64
#define BH_ 32
#define TOK_ 8192
#define OUT_ELEMS 4194304ull
#define ATTN_ELEMS 134217728ull
#define PO_ 4194304ull

__device__ uint16_t g_xnh[3ull * TOK_ * D_];
__device__ uint16_t g_xnl[3ull * TOK_ * D_];
__device__ uint16_t g_wh[4ull * 512 * 512];
__device__ uint16_t g_wl[4ull * 512 * 512];
__device__ uint16_t g_phh[3ull * PO_];
__device__ uint16_t g_phl[3ull * PO_];
__device__ uint16_t g_xh[(size_t)TOK_ * D_];
__device__ uint16_t g_xl[(size_t)TOK_ * D_];
__device__ float g_rinv[BH_ * S_];
__device__ float g_posF[(size_t)S_ * S_];
__device__ float g_attn_scratch[ATTN_ELEMS];

__device__ __forceinline__ void hmma(float c[4], const uint32_t a[4], uint32_t b0, uint32_t b1) {
    asm("mma.sync.aligned.m16n8k16.row.col.f32.bf16.bf16.f32 "
        "{%0,%1,%2,%3},{%4,%5,%6,%7},{%8,%9},{%0,%1,%2,%3};"
        : "+f"(c[0]), "+f"(c[1]), "+f"(c[2]), "+f"(c[3])
        : "r"(a[0]), "r"(a[1]), "r"(a[2]), "r"(a[3]), "r"(b0), "r"(b1));
}
__device__ __forceinline__ void ldsm4(uint32_t& r0, uint32_t& r1, uint32_t& r2, uint32_t& r3,
                                      uint32_t addr) {
    asm volatile("ldmatrix.sync.aligned.m8n8.x4.shared.b16 {%0,%1,%2,%3}, [%4];"
                 : "=r"(r0), "=r"(r1), "=r"(r2), "=r"(r3) : "r"(addr));
}
__device__ __forceinline__ void ldsm4t(uint32_t& r0, uint32_t& r1, uint32_t& r2, uint32_t& r3,
                                       uint32_t addr) {
    asm volatile("ldmatrix.sync.aligned.m8n8.x4.trans.shared.b16 {%0,%1,%2,%3}, [%4];"
                 : "=r"(r0), "=r"(r1), "=r"(r2), "=r"(r3) : "r"(addr));
}
__device__ __forceinline__ void cpa16(uint32_t dst, const void* src) {
    asm volatile("cp.async.cg.shared.global [%0], [%1], 16;" :: "r"(dst), "l"(src));
}
#define CP_COMMIT() asm volatile("cp.async.commit_group;")
#define CP_WAIT0()  asm volatile("cp.async.wait_group 0;")
#define CP_WAIT1()  asm volatile("cp.async.wait_group 1;")
__device__ __forceinline__ void splitpack(float f0, float f1, uint32_t& h, uint32_t& l) {
    asm("cvt.rn.bf16x2.f32 %0, %1, %2;" : "=r"(h) : "f"(f1), "f"(f0));
    float g0 = __uint_as_float(h << 16);
    float g1 = __uint_as_float(h & 0xffff0000u);
    asm("cvt.rn.bf16x2.f32 %0, %1, %2;" : "=r"(l) : "f"(f1 - g1), "f"(f0 - g0));
}
__device__ __forceinline__ float fexp(float x) {
    float t = x * 1.4426950408889634f;
    t = fmaxf(t, -126.0f);
    float z = t + 12582912.0f;
    int   n = (__float_as_int(z) & 0x7FFFFF) - 0x400000;
    float f = t - (z - 12582912.0f);
    float p = 1.5403530e-4f;
    p = fmaf(p, f, 1.3333558e-3f);
    p = fmaf(p, f, 9.6181291e-3f);
    p = fmaf(p, f, 5.5504109e-2f);
    p = fmaf(p, f, 2.4022651e-1f);
    p = fmaf(p, f, 6.9314718e-1f);
    p = fmaf(p, f, 1.0f);
    return __int_as_float(__float_as_int(p) + (n << 23));
}

// ---------------- K1: LayerNorm -> split bf16 ----------------
__global__ void ln_split(const float* __restrict__ q, const float* __restrict__ k,
                         const float* __restrict__ v, const float* __restrict__ w,
                         const float* __restrict__ b,
                         uint16_t* __restrict__ xh, uint16_t* __restrict__ xl) {
    const int row = blockIdx.x, which = blockIdx.y, tid = threadIdx.x;
    const float* src = (which == 0) ? q : (which == 1) ? k : v;
    float4 x = *(const float4*)(src + (size_t)row * D_ + tid * 4);
    float s  = x.x + x.y + x.z + x.w;
    float ss = x.x * x.x + x.y * x.y + x.z * x.z + x.w * x.w;
    __shared__ float red[2][4];
    #pragma unroll
    for (int o = 16; o; o >>= 1) {
        s  += __shfl_xor_sync(0xffffffffu, s, o);
        ss += __shfl_xor_sync(0xffffffffu, ss, o);
    }
    if ((tid & 31) == 0) { red[0][tid >> 5] = s; red[1][tid >> 5] = ss; }
    __syncthreads();
    s  = red[0][0] + red[0][1] + red[0][2] + red[0][3];
    ss = red[1][0] + red[1][1] + red[1][2] + red[1][3];
    const float mu  = s * (1.0f / D_);
    const float var = ss * (1.0f / D_) - mu * mu;
    const float r   = rsqrtf(var + 1e-5f);
    float4 wv = *(const float4*)(w + tid * 4);
    float4 bv = *(const float4*)(b + tid * 4);
    float o0 = (x.x - mu) * r * wv.x + bv.x;
    float o1 = (x.y - mu) * r * wv.y + bv.y;
    float o2 = (x.z - mu) * r * wv.z + bv.z;
    float o3 = (x.w - mu) * r * wv.w + bv.w;
    uint32_t h01, l01, h23, l23;
    splitpack(o0, o1, h01, l01); splitpack(o2, o3, h23, l23);
    size_t base = ((size_t)which * TOK_ + row) * D_ + tid * 4;
    *(uint32_t*)(xh + base) = h01; *(uint32_t*)(xh + base + 2) = h23;
    *(uint32_t*)(xl + base) = l01; *(uint32_t*)(xl + base + 2) = l23;
}

// ---------------- K2: split weights ----------------
__global__ void wsplit(const float* __restrict__ Wq, const float* __restrict__ Wk,
                       const float* __restrict__ Wv, const float* __restrict__ Wo,
                       uint16_t* __restrict__ wh, uint16_t* __restrict__ wl) {
    const int row = blockIdx.x, mat = blockIdx.y, tid = threadIdx.x;
    const float* W = (mat == 0) ? Wq : (mat == 1) ? Wk : (mat == 2) ? Wv : Wo;
    float4 x = *(const float4*)(W + (size_t)row * 512 + tid * 4);
    uint32_t h01, l01, h23, l23;
    splitpack(x.x, x.y, h01, l01); splitpack(x.z, x.w, h23, l23);
    size_t base = ((size_t)mat * 512 + row) * 512 + tid * 4;
    *(uint32_t*)(wh + base) = h01; *(uint32_t*)(wh + base + 2) = h23;
    *(uint32_t*)(wl + base) = l01; *(uint32_t*)(wl + base + 2) = l23;
}

// ---------------- K2b: permute pos into MMA-fragment-major layout ----------------
// posF[((qt*32+kt)*8+nt)*8+w][lane] float4 = {pos[r0][c], pos[r0][c+1], pos[r1][c], pos[r1][c+1]}
__global__ void pos_perm(const float* __restrict__ pos, float* __restrict__ posF) {
    int idx = blockIdx.x * 256 + threadIdx.x;     // 0..1048575 (float4 index)
    int lane = idx & 31;
    int w    = (idx >> 5) & 7;
    int nt   = (idx >> 8) & 7;
    int kt   = (idx >> 11) & 31;
    int qt   = idx >> 16;
    int r0   = qt * 128 + w * 16 + (lane >> 2);
    int col  = kt * 64 + nt * 8 + 2 * (lane & 3);
    float2 a = *(const float2*)(pos + (size_t)r0 * S_ + col);
    float2 b = *(const float2*)(pos + (size_t)(r0 + 8) * S_ + col);
    ((float4*)posF)[idx] = make_float4(a.x, a.y, b.x, b.y);
}

// ---------------- K3: batched projections / K5: out-proj + parallel rescale ----------------
__global__ __launch_bounds__(256, 2)
void gemm_mma(const uint16_t* __restrict__ Ab, const uint16_t* __restrict__ Alb,
              const uint16_t* __restrict__ Bb, const uint16_t* __restrict__ Blb,
              const float* __restrict__ b0p, const float* __restrict__ b1p,
              const float* __restrict__ b2p,
              uint16_t* __restrict__ Dh, uint16_t* __restrict__ Dl,
              float* __restrict__ Df, int mode,
              float* __restrict__ attn, const float* __restrict__ rinvp) {
    extern __shared__ uint16_t sm[];
    const int tid = threadIdx.x;
    if (mode == 0 && blockIdx.z >= 1) {
        int rid = (blockIdx.z - 1) * 256 + blockIdx.y * 4 + blockIdx.x;
        int bh = rid >> 4, r0 = (rid & 15) * 128;
        for (int rg = 0; rg < 32; rg++) {
            int br = r0 + rg * 4;
            float inv0 = rinvp[bh * S_ + br];
            float inv1 = rinvp[bh * S_ + br + 1];
            float inv2 = rinvp[bh * S_ + br + 2];
            float inv3 = rinvp[bh * S_ + br + 3];
            float4* p0 = (float4*)(attn + ((size_t)bh * S_ + br) * S_);
            float4* p1 = (float4*)(attn + ((size_t)bh * S_ + br + 1) * S_);
            float4* p2 = (float4*)(attn + ((size_t)bh * S_ + br + 2) * S_);
            float4* p3 = (float4*)(attn + ((size_t)bh * S_ + br + 3) * S_);
            float4 a0 = p0[tid], b0 = p0[tid + 256];
            float4 a1 = p1[tid], b1 = p1[tid + 256];
            float4 a2 = p2[tid], b2 = p2[tid + 256];
            float4 a3 = p3[tid], b3 = p3[tid + 256];
            a0.x *= inv0; a0.y *= inv0; a0.z *= inv0; a0.w *= inv0;
            b0.x *= inv0; b0.y *= inv0; b0.z *= inv0; b0.w *= inv0;
            a1.x *= inv1; a1.y *= inv1; a1.z *= inv1; a1.w *= inv1;
            b1.x *= inv1; b1.y *= inv1; b1.z *= inv1; b1.w *= inv1;
            a2.x *= inv2; a2.y *= inv2; a2.z *= inv2; a2.w *= inv2;
            b2.x *= inv2; b2.y *= inv2; b2.z *= inv2; b2.w *= inv2;
            a3.x *= inv3; a3.y *= inv3; a3.z *= inv3; a3.w *= inv3;
            b3.x *= inv3; b3.y *= inv3; b3.z *= inv3; b3.w *= inv3;
            p0[tid] = a0; p0[tid + 256] = b0;
            p1[tid] = a1; p1[tid + 256] = b1;
            p2[tid] = a2; p2[tid + 256] = b2;
            p3[tid] = a3; p3[tid + 256] = b3;
        }
        return;
    }
    const int w = tid >> 5, lane = tid & 31;
    const int gid = lane >> 2, tig = lane & 3;
    const int n0 = blockIdx.x * 128, m0 = blockIdx.y * 128;
    const int mz = (mode == 1) ? blockIdx.z : 0;
    const uint16_t* Ah = Ab  + (size_t)mz * TOK_ * D_;
    const uint16_t* Al = Alb + (size_t)mz * TOK_ * D_;
    const uint16_t* Bh = Bb  + (size_t)mz * 512 * 512;
    const uint16_t* Bl = Blb + (size_t)mz * 512 * 512;
    const float* bias = (mz == 0) ? b0p : (mz == 1) ? b1p : b2p;
    const int wm = w >> 2, wn = w & 3;
    const uint32_t sbase = (uint32_t)__cvta_generic_to_shared(sm);
    const int srow = tid >> 1;
    const uint32_t soff = (uint32_t)(srow * 80 + (tid & 1) * 32);
    const size_t goff = (size_t)srow * 512 + (tid & 1) * 16;
    const uint32_t loA = (lane & 15) * 80 + (lane >> 4) * 16;
    const uint32_t loB = (lane & 7) * 80 + (lane >> 3) * 16;

    float acc[4][4][4];
    #pragma unroll
    for (int i = 0; i < 4; i++)
        #pragma unroll
        for (int j = 0; j < 4; j++)
            #pragma unroll
            for (int kq = 0; kq < 4; kq++) acc[i][j][kq] = 0.f;

    {
        uint32_t b = sbase;
        cpa16(b + soff,          Ah + (size_t)m0 * 512 + goff);
        cpa16(b + soff + 16,     Ah + (size_t)m0 * 512 + goff + 8);
        cpa16(b + 10240 + soff,      Al + (size_t)m0 * 512 + goff);
        cpa16(b + 10240 + soff + 16, Al + (size_t)m0 * 512 + goff + 8);
        cpa16(b + 20480 + soff,      Bh + (size_t)n0 * 512 + goff);
        cpa16(b + 20480 + soff + 16, Bh + (size_t)n0 * 512 + goff + 8);
        cpa16(b + 30720 + soff,      Bl + (size_t)n0 * 512 + goff);
        cpa16(b + 30720 + soff + 16, Bl + (size_t)n0 * 512 + goff + 8);
        CP_COMMIT();
    }
    for (int c = 0; c < 16; c++) {
        if (c + 1 < 16) {
            uint32_t b = sbase + ((c + 1) & 1) * 40960;
            size_t g = goff + (c + 1) * 32;
            cpa16(b + soff,          Ah + (size_t)m0 * 512 + g);
            cpa16(b + soff + 16,     Ah + (size_t)m0 * 512 + g + 8);
            cpa16(b + 10240 + soff,      Al + (size_t)m0 * 512 + g);
            cpa16(b + 10240 + soff + 16, Al + (size_t)m0 * 512 + g + 8);
            cpa16(b + 20480 + soff,      Bh + (size_t)n0 * 512 + g);
            cpa16(b + 20480 + soff + 16, Bh + (size_t)n0 * 512 + g + 8);
            cpa16(b + 30720 + soff,      Bl + (size_t)n0 * 512 + g);
            cpa16(b + 30720 + soff + 16, Bl + (size_t)n0 * 512 + g + 8);
            CP_COMMIT();
            CP_WAIT1();
        } else {
            CP_WAIT0();
        }
        __syncthreads();
        const uint32_t aB  = sbase + (c & 1) * 40960;
        const uint32_t alB = aB + 10240;
        const uint32_t bB  = aB + 20480;
        const uint32_t blB = aB + 30720;

        uint32_t bhf[4][4], blf[4][4];
        #pragma unroll
        for (int nt = 0; nt < 4; nt++) {
            uint32_t br = (uint32_t)(wn * 32 + nt * 8) * 80;
            ldsm4(bhf[nt][0], bhf[nt][1], bhf[nt][2], bhf[nt][3], bB + br + loB);
            ldsm4(blf[nt][0], blf[nt][1], blf[nt][2], blf[nt][3], blB + br + loB);
        }
        #pragma unroll
        for (int ks = 0; ks < 2; ks++) {
            uint32_t ah[4][4], al[4][4];
            #pragma unroll
            for (int mt = 0; mt < 4; mt++) {
                uint32_t ab = (uint32_t)((wm * 64 + mt * 16) * 80 + ks * 32);
                ldsm4(ah[mt][0], ah[mt][1], ah[mt][2], ah[mt][3], aB + ab + loA);
                ldsm4(al[mt][0], al[mt][1], al[mt][2], al[mt][3], alB + ab + loA);
            }
            #pragma unroll
            for (int mt = 0; mt < 4; mt++)
                #pragma unroll
                for (int nt = 0; nt < 4; nt++) {
                    hmma(acc[mt][nt], ah[mt], bhf[nt][2 * ks], bhf[nt][2 * ks + 1]);
                    hmma(acc[mt][nt], al[mt], bhf[nt][2 * ks], bhf[nt][2 * ks + 1]);
                    hmma(acc[mt][nt], ah[mt], blf[nt][2 * ks], blf[nt][2 * ks + 1]);
                }
        }
        __syncthreads();
    }
    #pragma unroll
    for (int mt = 0; mt < 4; mt++) {
        int row0 = m0 + wm * 64 + mt * 16 + gid, row1 = row0 + 8;
        #pragma unroll
        for (int nt = 0; nt < 4; nt++) {
            int nc = n0 + wn * 32 + nt * 8 + 2 * tig;
            float b0 = bias[nc], b1 = bias[nc + 1];
            float c00 = acc[mt][nt][0] + b0, c01 = acc[mt][nt][1] + b1;
            float c10 = acc[mt][nt][2] + b0, c11 = acc[mt][nt][3] + b1;
            if (mode == 0) {
                *(float2*)(Df + (size_t)row0 * 512 + nc) = make_float2(c00, c01);
                *(float2*)(Df + (size_t)row1 * 512 + nc) = make_float2(c10, c11);
            } else {
                int h = nc >> 6, dd = nc & 63;
                uint32_t hh, ll;
                int bb = row0 >> 11, tk = row0 & 2047;
                size_t o = ((size_t)mz * PO_) + (((size_t)(bb * H_ + h)) * S_ + tk) * DK_ + dd;
                splitpack(c00, c01, hh, ll);
                *(uint32_t*)(Dh + o) = hh; *(uint32_t*)(Dl + o) = ll;
                bb = row1 >> 11; tk = row1 & 2047;
                o = ((size_t)mz * PO_) + (((size_t)(bb * H_ + h)) * S_ + tk) * DK_ + dd;
                splitpack(c10, c11, hh, ll);
                *(uint32_t*)(Dh + o) = hh; *(uint32_t*)(Dl + o) = ll;
            }
        }
    }
}

// ---------------- K4: fused attention (coalesced posF loads) ----------------
__global__ __launch_bounds__(256, 2)
void attn_mma(const uint16_t* __restrict__ ph, const uint16_t* __restrict__ pl,
              const float* __restrict__ posF, float* __restrict__ attn,
              float* __restrict__ rinv,
              uint16_t* __restrict__ xh, uint16_t* __restrict__ xl) {
    extern __shared__ uint16_t sm[];
    uint16_t* QH  = sm;
    uint16_t* QL  = sm + 9216;
    const int tid = threadIdx.x, w = tid >> 5, lane = tid & 31;
    const int gid = lane >> 2, tig = lane & 3;
    const int qt = blockIdx.x, bh = blockIdx.y, q0 = qt * 128;
    const uint16_t* qg  = ph;
    const uint16_t* qgl = pl;
    const uint16_t* kg  = ph + PO_;
    const uint16_t* kgl = pl + PO_;
    const uint16_t* vg  = ph + 2 * PO_;
    const uint16_t* vgl = pl + 2 * PO_;

    const uint32_t sbase = (uint32_t)__cvta_generic_to_shared(sm);
    const uint32_t loK = (lane & 7) * 144 + (lane >> 3) * 16;
    const uint32_t loV = (lane & 15) * 144 + (lane >> 4) * 16;
    const int vrow = tid >> 2;
    const uint32_t voff = (uint32_t)(vrow * 144 + (tid & 3) * 32);
    const size_t vgoff = (size_t)(tid & 3) * 16;

    {
        int row = tid >> 1, half = (tid & 1) * 32;
        const uint4* s1 = (const uint4*)(qg  + ((size_t)bh * S_ + q0 + row) * DK_ + half);
        const uint4* s2 = (const uint4*)(qgl + ((size_t)bh * S_ + q0 + row) * DK_ + half);
        uint4* d1 = (uint4*)(QH + row * 72 + half);
        uint4* d2 = (uint4*)(QL + row * 72 + half);
        #pragma unroll
        for (int j = 0; j < 4; j++) { d1[j] = s1[j]; d2[j] = s2[j]; }
    }
    __syncthreads();
    uint32_t qfh[4][4], qfl[4][4];
    {
        int qr = w * 16 + gid;
        #pragma unroll
        for (int ks = 0; ks < 4; ks++) {
            int dc = ks * 16 + 2 * tig;
            qfh[ks][0] = *(const uint32_t*)(QH + qr * 72 + dc);
            qfh[ks][1] = *(const uint32_t*)(QH + (qr + 8) * 72 + dc);
            qfh[ks][2] = *(const uint32_t*)(QH + qr * 72 + dc + 8);
            qfh[ks][3] = *(const uint32_t*)(QH + (qr + 8) * 72 + dc + 8);
            qfl[ks][0] = *(const uint32_t*)(QL + qr * 72 + dc);
            qfl[ks][1] = *(const uint32_t*)(QL + (qr + 8) * 72 + dc);
            qfl[ks][2] = *(const uint32_t*)(QL + qr * 72 + dc + 8);
            qfl[ks][3] = *(const uint32_t*)(QL + (qr + 8) * 72 + dc + 8);
        }
    }
    __syncthreads();

    const int r0 = q0 + w * 16 + gid, r1 = r0 + 8;
    float sum0 = 0.f, sum1 = 0.f;
    float accv[8][4];
    #pragma unroll
    for (int i = 0; i < 8; i++)
        #pragma unroll
        for (int j = 0; j < 4; j++) accv[i][j] = 0.f;
    uint32_t a01h[4], a01l[4];

    {
        size_t g = ((size_t)bh * S_ + vrow) * DK_ + vgoff;
        uint32_t b = sbase;
        cpa16(b + voff,              kg + g);
        cpa16(b + voff + 16,         kg + g + 8);
        cpa16(b + 9216 + voff,       kgl + g);
        cpa16(b + 9216 + voff + 16,  kgl + g + 8);
        cpa16(b + 18432 + voff,      vg + g);
        cpa16(b + 18432 + voff + 16, vg + g + 8);
        cpa16(b + 27648 + voff,      vgl + g);
        cpa16(b + 27648 + voff + 16, vgl + g + 8);
        CP_COMMIT();
    }
    for (int kt = 0; kt < 32; kt++) {
        const int k0 = kt * 64;
        if (kt + 1 < 32) {
            size_t g = ((size_t)bh * S_ + (kt + 1) * 64 + vrow) * DK_ + vgoff;
            uint32_t b = sbase + ((kt + 1) & 1) * 36864;
            cpa16(b + voff,              kg + g);
            cpa16(b + voff + 16,         kg + g + 8);
            cpa16(b + 9216 + voff,       kgl + g);
            cpa16(b + 9216 + voff + 16,  kgl + g + 8);
            cpa16(b + 18432 + voff,      vg + g);
            cpa16(b + 18432 + voff + 16, vg + g + 8);
            cpa16(b + 27648 + voff,      vgl + g);
            cpa16(b + 27648 + voff + 16, vgl + g + 8);
            CP_COMMIT();
            CP_WAIT1();
        } else {
            CP_WAIT0();
        }
        __syncthreads();
        const uint32_t bb0 = sbase + (kt & 1) * 36864;
        const uint32_t khb = bb0, klb = bb0 + 9216;
        const uint32_t vshb = bb0 + 18432, vslb = bb0 + 27648;
        const float* pbase = posF + (size_t)(qt * 32 + kt) * 8192 + w * 128 + lane * 4;

        #pragma unroll
        for (int nt = 0; nt < 8; nt++) {
            float s[4] = {0.f, 0.f, 0.f, 0.f};
            uint32_t kb[8], klo[8];
            ldsm4(kb[0], kb[1], kb[2], kb[3], khb + nt * 1152 + loK);
            ldsm4(kb[4], kb[5], kb[6], kb[7], khb + nt * 1152 + 64 + loK);
            ldsm4(klo[0], klo[1], klo[2], klo[3], klb + nt * 1152 + loK);
            ldsm4(klo[4], klo[5], klo[6], klo[7], klb + nt * 1152 + 64 + loK);
            #pragma unroll
            for (int ks = 0; ks < 4; ks++) {
                hmma(s, qfh[ks], kb[2 * ks], kb[2 * ks + 1]);
                hmma(s, qfl[ks], kb[2 * ks], kb[2 * ks + 1]);
                hmma(s, qfh[ks], klo[2 * ks], klo[2 * ks + 1]);
            }
            float4 pf = *(const float4*)(pbase + nt * 1024);
            float e0 = fexp(fmaf(s[0], 0.125f, pf.x));
            float e1 = fexp(fmaf(s[1], 0.125f, pf.y));
            float e2 = fexp(fmaf(s[2], 0.125f, pf.z));
            float e3 = fexp(fmaf(s[3], 0.125f, pf.w));
            sum0 += e0 + e1; sum1 += e2 + e3;
            int col = k0 + nt * 8 + 2 * tig;
            *(float2*)(attn + ((size_t)bh * S_ + r0) * S_ + col) = make_float2(e0, e1);
            *(float2*)(attn + ((size_t)bh * S_ + r1) * S_ + col) = make_float2(e2, e3);
            uint32_t h0, l0, h1, l1;
            splitpack(e0, e1, h0, l0);
            splitpack(e2, e3, h1, l1);
            if ((nt & 1) == 0) {
                a01h[0] = h0; a01h[1] = h1; a01l[0] = l0; a01l[1] = l1;
            } else {
                a01h[2] = h0; a01h[3] = h1; a01l[2] = l0; a01l[3] = l1;
                int kc = nt >> 1;
                #pragma unroll
                for (int dtp = 0; dtp < 4; dtp++) {
                    uint32_t vh4[4], vl4[4];
                    ldsm4t(vh4[0], vh4[1], vh4[2], vh4[3], vshb + kc * 2304 + dtp * 32 + loV);
                    ldsm4t(vl4[0], vl4[1], vl4[2], vl4[3], vslb + kc * 2304 + dtp * 32 + loV);
                    hmma(accv[2 * dtp],     a01h, vh4[0], vh4[1]);
                    hmma(accv[2 * dtp],     a01l, vh4[0], vh4[1]);
                    hmma(accv[2 * dtp],     a01h, vl4[0], vl4[1]);
                    hmma(accv[2 * dtp + 1], a01h, vh4[2], vh4[3]);
                    hmma(accv[2 * dtp + 1], a01l, vh4[2], vh4[3]);
                    hmma(accv[2 * dtp + 1], a01h, vl4[2], vl4[3]);
                }
            }
        }
        __syncthreads();
    }
    sum0 += __shfl_xor_sync(0xffffffffu, sum0, 1);
    sum0 += __shfl_xor_sync(0xffffffffu, sum0, 2);
    sum1 += __shfl_xor_sync(0xffffffffu, sum1, 1);
    sum1 += __shfl_xor_sync(0xffffffffu, sum1, 2);
    float inv0 = 1.f / sum0, inv1 = 1.f / sum1;
    if (tig == 0) { rinv[bh * S_ + r0] = inv0; rinv[bh * S_ + r1] = inv1; }
    const int bb = bh >> 3, h = bh & 7;
    #pragma unroll
    for (int dt = 0; dt < 8; dt++) {
        int col = dt * 8 + 2 * tig;
        uint32_t hh, ll;
        splitpack(accv[dt][0] * inv0, accv[dt][1] * inv0, hh, ll);
        *(uint32_t*)(xh + ((size_t)(bb * S_ + r0)) * D_ + h * DK_ + col) = hh;
        *(uint32_t*)(xl + ((size_t)(bb * S_ + r0)) * D_ + h * DK_ + col) = ll;
        splitpack(accv[dt][2] * inv1, accv[dt][3] * inv1, hh, ll);
        *(uint32_t*)(xh + ((size_t)(bb * S_ + r1)) * D_ + h * DK_ + col) = hh;
        *(uint32_t*)(xl + ((size_t)(bb * S_ + r1)) * D_ + h * DK_ + col) = ll;
    }
}

// ---------------- launch ----------------
extern "C" void kernel_launch(void* const* d_in, const int* in_sizes, int n_in,
                              void* d_out, int out_size) {
    const float* q     = (const float*)d_in[0];
    const float* k     = (const float*)d_in[1];
    const float* v     = (const float*)d_in[2];
    const float* pos_k = (const float*)d_in[4];
    const float* ln_w  = (const float*)d_in[5];
    const float* ln_b  = (const float*)d_in[6];
    const float* Wq    = (const float*)d_in[7];
    const float* bq    = (const float*)d_in[8];
    const float* Wk    = (const float*)d_in[9];
    const float* bk    = (const float*)d_in[10];
    const float* Wv    = (const float*)d_in[11];
    const float* bv    = (const float*)d_in[12];
    const float* Wo    = (const float*)d_in[13];
    const float* bo    = (const float*)d_in[14];
    float* out = (float*)d_out;

    uint16_t *xnh, *xnl, *wh, *wl, *phh, *phl, *xh, *xl;
    float *rinv, *attn, *posF;
    cudaGetSymbolAddress((void**)&xnh, g_xnh);
    cudaGetSymbolAddress((void**)&xnl, g_xnl);
    cudaGetSymbolAddress((void**)&wh, g_wh);
    cudaGetSymbolAddress((void**)&wl, g_wl);
    cudaGetSymbolAddress((void**)&phh, g_phh);
    cudaGetSymbolAddress((void**)&phl, g_phl);
    cudaGetSymbolAddress((void**)&xh, g_xh);
    cudaGetSymbolAddress((void**)&xl, g_xl);
    cudaGetSymbolAddress((void**)&rinv, g_rinv);
    cudaGetSymbolAddress((void**)&posF, g_posF);
    if ((size_t)out_size >= OUT_ELEMS + ATTN_ELEMS) {
        attn = out + OUT_ELEMS;
    } else {
        cudaGetSymbolAddress((void**)&attn, g_attn_scratch);
    }

    cudaFuncSetAttribute(gemm_mma, cudaFuncAttributeMaxDynamicSharedMemorySize, 81920);
    cudaFuncSetAttribute(attn_mma, cudaFuncAttributeMaxDynamicSharedMemorySize, 73728);

    ln_split<<<dim3(TOK_, 3), 128>>>(q, k, v, ln_w, ln_b, xnh, xnl);
    wsplit<<<dim3(512, 4), 128>>>(Wq, Wk, Wv, Wo, wh, wl);
    pos_perm<<<4096, 256>>>(pos_k, posF);

    const size_t WO = 512ull * 512ull;
    gemm_mma<<<dim3(4, 64, 3), 256, 81920>>>(xnh, xnl, wh, wl, bq, bk, bv,
                                             phh, phl, nullptr, 1, nullptr, nullptr);
    attn_mma<<<dim3(16, 32), 256, 73728>>>(phh, phl, posF, attn, rinv, xh, xl);
    gemm_mma<<<dim3(4, 64, 3), 256, 81920>>>(xh, xl, wh + 3 * WO, wl + 3 * WO,
                                             bo, bo, bo, nullptr, nullptr, out, 0,
                                             attn, rinv);
}